// round 5
// baseline (speedup 1.0000x reference)
#include <cuda_runtime.h>
#include <cstdint>

// B=2,H=16,S=2048,D=64 causal attention, fp32 in/out.
#define BHN   32
#define SEQ   2048
#define DH    64
#define BM    128
#define BN    64
#define NTHR  256
#define NELEM (BHN * SEQ * DH)          // 4,194,304

#define QSCALE 0.18033688f              // 0.125 * log2(e)

// ---- pre-converted bf16 operands (hi/lo split), row = 64 bf16 = 128 B ----
__device__ __align__(16) uint8_t gQhi[NELEM * 2];
__device__ __align__(16) uint8_t gQlo[NELEM * 2];
__device__ __align__(16) uint8_t gKhi[NELEM * 2];
__device__ __align__(16) uint8_t gKlo[NELEM * 2];
__device__ __align__(16) uint8_t gVhi[NELEM * 2];
__device__ __align__(16) uint8_t gVlo[NELEM * 2];

// ---- smem: 3 stages x 32KB (KHI|KLO|VHI|VLO, 8KB each, XOR-swizzled) ----
#define STAGE   32768
#define P_KHI   0
#define P_KLO   8192
#define P_VHI   16384
#define P_VLO   24576
#define SMEM_BYTES (3 * STAGE)          // 98304

__device__ __forceinline__ uint32_t smem_u32(const void* p) {
    uint32_t a;
    asm("{ .reg .u64 t; cvta.to.shared.u64 t, %1; cvt.u32.u64 %0, t; }" : "=r"(a) : "l"(p));
    return a;
}
__device__ __forceinline__ uint32_t swz(uint32_t b) { return b ^ ((b >> 3) & 0x70u); }

__device__ __forceinline__ void cpa16(uint32_t dst, const void* src) {
    asm volatile("cp.async.cg.shared.global [%0], [%1], 16;" :: "r"(dst), "l"(src));
}
#define CP_COMMIT() asm volatile("cp.async.commit_group;" ::: "memory")
#define CP_WAIT(n)  asm volatile("cp.async.wait_group %0;" :: "n"(n) : "memory")

__device__ __forceinline__ void ldsm4(uint32_t r[4], uint32_t addr) {
    asm volatile("ldmatrix.sync.aligned.m8n8.x4.shared.b16 {%0,%1,%2,%3}, [%4];"
        : "=r"(r[0]), "=r"(r[1]), "=r"(r[2]), "=r"(r[3]) : "r"(addr));
}
__device__ __forceinline__ void ldsm4t(uint32_t r[4], uint32_t addr) {
    asm volatile("ldmatrix.sync.aligned.m8n8.x4.trans.shared.b16 {%0,%1,%2,%3}, [%4];"
        : "=r"(r[0]), "=r"(r[1]), "=r"(r[2]), "=r"(r[3]) : "r"(addr));
}
__device__ __forceinline__ void mma_bf16(float c[4], const uint32_t a[4],
                                         uint32_t b0, uint32_t b1) {
    asm volatile("mma.sync.aligned.m16n8k16.row.col.f32.bf16.bf16.f32 "
        "{%0,%1,%2,%3}, {%4,%5,%6,%7}, {%8,%9}, {%0,%1,%2,%3};"
        : "+f"(c[0]), "+f"(c[1]), "+f"(c[2]), "+f"(c[3])
        : "r"(a[0]), "r"(a[1]), "r"(a[2]), "r"(a[3]), "r"(b0), "r"(b1));
}
__device__ __forceinline__ uint32_t packbf(float lo, float hi) {
    uint32_t r;
    asm("cvt.rn.bf16x2.f32 %0, %1, %2;" : "=r"(r) : "f"(hi), "f"(lo));
    return r;
}
__device__ __forceinline__ void split2(float x, float y, uint32_t& h, uint32_t& l) {
    h = packbf(x, y);
    float hx = __uint_as_float(h << 16);
    float hy = __uint_as_float(h & 0xffff0000u);
    l = packbf(x - hx, y - hy);
}

// ================= pre-pass: fp32 -> bf16 hi/lo =================
__global__ __launch_bounds__(256)
void prep_kernel(const float* __restrict__ Qg,
                 const float* __restrict__ Kg,
                 const float* __restrict__ Vg)
{
    const int i = blockIdx.x * 256 + threadIdx.x;      // per float4
    const int t = blockIdx.y;                          // 0=Q 1=K 2=V
    const float4* src = (t == 0) ? (const float4*)Qg
                      : (t == 1) ? (const float4*)Kg : (const float4*)Vg;
    uint2* hi = (t == 0) ? (uint2*)gQhi : (t == 1) ? (uint2*)gKhi : (uint2*)gVhi;
    uint2* lo = (t == 0) ? (uint2*)gQlo : (t == 1) ? (uint2*)gKlo : (uint2*)gVlo;

    float4 v = src[i];
    if (t == 0) { v.x *= QSCALE; v.y *= QSCALE; v.z *= QSCALE; v.w *= QSCALE; }
    uint2 h, l;
    split2(v.x, v.y, h.x, l.x);
    split2(v.z, v.w, h.y, l.y);
    hi[i] = h;
    lo[i] = l;
}

// ================= main attention kernel =================
__global__ __launch_bounds__(NTHR, 1)
void fattn_mma_kernel(float* __restrict__ Og,
                      const float* __restrict__ Qunused)
{
    extern __shared__ __align__(1024) uint8_t smem[];
    const uint32_t sb = smem_u32(smem);

    const int tid  = threadIdx.x;
    const int w    = tid >> 5;
    const int lane = tid & 31;
    const int lr   = lane & 15;
    const int lc   = (lane >> 4) << 3;
    const int quad = lane & 3;

    const int qt = (gridDim.x - 1) - blockIdx.x;   // heavy tiles first
    const int bh = blockIdx.y;
    const size_t rowbase = (size_t)bh * SEQ;       // row index base (128B rows)

    // ---- issue Q (hi 16KB + lo 16KB) into stage1+2 region via cp.async ----
    {
        const uint8_t* qh_src = gQhi + (rowbase + (size_t)qt * BM) * 128;
        const uint8_t* ql_src = gQlo + (rowbase + (size_t)qt * BM) * 128;
        #pragma unroll
        for (int j = 0; j < 4; j++) {              // 1024 chunks / 256 thr
            uint32_t idx = (uint32_t)(tid + j * NTHR);
            uint32_t off = idx << 4;
            cpa16(sb + STAGE + swz(off),          qh_src + off);
            cpa16(sb + STAGE + 16384 + swz(off),  ql_src + off);
        }
        CP_COMMIT();
    }

    const int n_kv = 2 * qt + 2;

    // tile issuer: 512 chunks x 4 parts / 256 thr = 8 cp.async per thread
    auto issue_tile = [&](int kt, uint32_t stg) {
        const size_t tb = (rowbase + (size_t)kt * BN) * 128;
        const uint8_t* kh = gKhi + tb;  const uint8_t* kl = gKlo + tb;
        const uint8_t* vh = gVhi + tb;  const uint8_t* vl = gVlo + tb;
        #pragma unroll
        for (int j = 0; j < 2; j++) {
            uint32_t idx = (uint32_t)(tid + j * NTHR);
            uint32_t off = idx << 4;
            uint32_t so  = sb + stg + swz(off);
            cpa16(so + P_KHI, kh + off);
            cpa16(so + P_KLO, kl + off);
            cpa16(so + P_VHI, vh + off);
            cpa16(so + P_VLO, vl + off);
        }
        CP_COMMIT();
    };

    issue_tile(0, 0);                   // stage 0

    // ---- wait Q, load persistent Q fragments ----
    CP_WAIT(1);
    __syncthreads();
    uint32_t qh[4][4], ql[4][4];
    {
        uint32_t rowb = (uint32_t)((w * 16 + lr) * 128);
        #pragma unroll
        for (int ks = 0; ks < 4; ks++) {
            uint32_t a = sb + STAGE + swz(rowb + (uint32_t)((ks * 16 + lc) * 2));
            ldsm4(qh[ks], a);
            ldsm4(ql[ks], a + 16384);
        }
    }
    __syncthreads();                    // Q region (stage1+2) now free
    issue_tile(1, STAGE);               // stage 1 (n_kv >= 2 always)

    float o[8][4];
    #pragma unroll
    for (int n = 0; n < 8; n++)
        #pragma unroll
        for (int j = 0; j < 4; j++) o[n][j] = 0.f;
    float m0 = -1e30f, m1 = -1e30f, l0 = 0.f, l1 = 0.f;

    const int qg0 = qt * BM + w * 16 + (lane >> 2);
    const uint32_t lrow128 = (uint32_t)(lr * 128);

    for (int kt = 0; kt < n_kv; kt++) {
        CP_WAIT(1);                     // tile kt resident
        __syncthreads();                // visible to all; prev stage reads done
        if (kt + 2 < n_kv) issue_tile(kt + 2, (uint32_t)((kt + 2) % 3) * STAGE);

        const uint32_t stg = sb + (uint32_t)(kt % 3) * STAGE;

        // ---- S = Qhi.Khi + Qlo.Khi + Qhi.Klo ----
        float s[8][4];
        #pragma unroll
        for (int n = 0; n < 8; n++)
            #pragma unroll
            for (int j = 0; j < 4; j++) s[n][j] = 0.f;

        #pragma unroll
        for (int ks = 0; ks < 4; ks++) {
            #pragma unroll
            for (int kg = 0; kg < 4; kg++) {
                uint32_t addr = stg + swz((uint32_t)((kg * 16 + lr) * 128)
                                          + (uint32_t)((ks * 16 + lc) * 2));
                uint32_t bhf[4], blf[4];
                ldsm4(bhf, addr + P_KHI);
                mma_bf16(s[2*kg],   qh[ks], bhf[0], bhf[2]);
                mma_bf16(s[2*kg+1], qh[ks], bhf[1], bhf[3]);
                mma_bf16(s[2*kg],   ql[ks], bhf[0], bhf[2]);
                mma_bf16(s[2*kg+1], ql[ks], bhf[1], bhf[3]);
                ldsm4(blf, addr + P_KLO);
                mma_bf16(s[2*kg],   qh[ks], blf[0], blf[2]);
                mma_bf16(s[2*kg+1], qh[ks], blf[1], blf[3]);
            }
        }

        // ---- causal mask (diagonal tiles only) ----
        if (kt >= 2 * qt) {
            #pragma unroll
            for (int n = 0; n < 8; n++) {
                int kb = kt * BN + n * 8 + quad * 2;
                if (kb     > qg0)     s[n][0] = -1e30f;
                if (kb + 1 > qg0)     s[n][1] = -1e30f;
                if (kb     > qg0 + 8) s[n][2] = -1e30f;
                if (kb + 1 > qg0 + 8) s[n][3] = -1e30f;
            }
        }

        // ---- online softmax (log2 domain; scale folded into Q) ----
        float mx0 = s[0][0], mx1 = s[0][2];
        #pragma unroll
        for (int n = 0; n < 8; n++) {
            mx0 = fmaxf(mx0, fmaxf(s[n][0], s[n][1]));
            mx1 = fmaxf(mx1, fmaxf(s[n][2], s[n][3]));
        }
        mx0 = fmaxf(mx0, __shfl_xor_sync(0xffffffffu, mx0, 1));
        mx0 = fmaxf(mx0, __shfl_xor_sync(0xffffffffu, mx0, 2));
        mx1 = fmaxf(mx1, __shfl_xor_sync(0xffffffffu, mx1, 1));
        mx1 = fmaxf(mx1, __shfl_xor_sync(0xffffffffu, mx1, 2));

        float mn0 = fmaxf(m0, mx0), mn1 = fmaxf(m1, mx1);
        float a0 = exp2f(m0 - mn0), a1 = exp2f(m1 - mn1);
        m0 = mn0; m1 = mn1;

        float rs0 = 0.f, rs1 = 0.f;
        #pragma unroll
        for (int n = 0; n < 8; n++) {
            s[n][0] = exp2f(s[n][0] - m0); rs0 += s[n][0];
            s[n][1] = exp2f(s[n][1] - m0); rs0 += s[n][1];
            s[n][2] = exp2f(s[n][2] - m1); rs1 += s[n][2];
            s[n][3] = exp2f(s[n][3] - m1); rs1 += s[n][3];
        }
        rs0 += __shfl_xor_sync(0xffffffffu, rs0, 1);
        rs0 += __shfl_xor_sync(0xffffffffu, rs0, 2);
        rs1 += __shfl_xor_sync(0xffffffffu, rs1, 1);
        rs1 += __shfl_xor_sync(0xffffffffu, rs1, 2);
        l0 = l0 * a0 + rs0;
        l1 = l1 * a1 + rs1;

        #pragma unroll
        for (int n = 0; n < 8; n++) {
            o[n][0] *= a0; o[n][1] *= a0;
            o[n][2] *= a1; o[n][3] *= a1;
        }

        // ---- P -> A-fragments (hi + residual), register-only ----
        uint32_t pa[4][4], pl[4][4];
        #pragma unroll
        for (int j = 0; j < 4; j++) {
            split2(s[2*j][0],   s[2*j][1],   pa[j][0], pl[j][0]);
            split2(s[2*j][2],   s[2*j][3],   pa[j][1], pl[j][1]);
            split2(s[2*j+1][0], s[2*j+1][1], pa[j][2], pl[j][2]);
            split2(s[2*j+1][2], s[2*j+1][3], pa[j][3], pl[j][3]);
        }

        // ---- O += Phi.Vhi + Plo.Vhi + Phi.Vlo ----
        #pragma unroll
        for (int ks = 0; ks < 4; ks++) {
            #pragma unroll
            for (int dg = 0; dg < 4; dg++) {
                uint32_t addr = stg + swz((uint32_t)((ks * 16 + lr) * 128)
                                          + (uint32_t)((dg * 16 + lc) * 2));
                uint32_t vhf[4], vlf[4];
                ldsm4t(vhf, addr + P_VHI);
                mma_bf16(o[2*dg],   pa[ks], vhf[0], vhf[1]);
                mma_bf16(o[2*dg+1], pa[ks], vhf[2], vhf[3]);
                mma_bf16(o[2*dg],   pl[ks], vhf[0], vhf[1]);
                mma_bf16(o[2*dg+1], pl[ks], vhf[2], vhf[3]);
                ldsm4t(vlf, addr + P_VLO);
                mma_bf16(o[2*dg],   pa[ks], vlf[0], vlf[1]);
                mma_bf16(o[2*dg+1], pa[ks], vlf[2], vlf[3]);
            }
        }
    }

    // ---- epilogue ----
    float inv0 = 1.0f / l0, inv1 = 1.0f / l1;
    float* Orow0 = Og + (rowbase + qg0) * DH;
    float* Orow1 = Orow0 + 8 * DH;
    #pragma unroll
    for (int n = 0; n < 8; n++) {
        int d = n * 8 + quad * 2;
        *(float2*)(Orow0 + d) = make_float2(o[n][0] * inv0, o[n][1] * inv0);
        *(float2*)(Orow1 + d) = make_float2(o[n][2] * inv1, o[n][3] * inv1);
    }
    (void)lrow128; (void)Qunused;
}

extern "C" void kernel_launch(void* const* d_in, const int* in_sizes, int n_in,
                              void* d_out, int out_size)
{
    const float* Q = (const float*)d_in[0];
    const float* K = (const float*)d_in[1];
    const float* V = (const float*)d_in[2];
    float* O = (float*)d_out;

    dim3 pgrid(NELEM / 4 / 256, 3);     // (4096, 3)
    prep_kernel<<<pgrid, 256>>>(Q, K, V);

    cudaFuncSetAttribute(fattn_mma_kernel,
                         cudaFuncAttributeMaxDynamicSharedMemorySize, SMEM_BYTES);
    dim3 grid(SEQ / BM, BHN);           // (16, 32)
    fattn_mma_kernel<<<grid, NTHR, SMEM_BYTES>>>(O, Q);
}

// round 6
// speedup vs baseline: 1.0003x; 1.0003x over previous
#include <cuda_runtime.h>
#include <cstdint>

// B=2,H=16,S=2048,D=64 causal attention, fp32 in/out.
#define BHN   32
#define SEQ   2048
#define DH    64
#define BM    128
#define BN    64
#define NTHR  256
#define NELEM (BHN * SEQ * DH)          // 4,194,304

#define QSCALE 0.18033688f              // 0.125 * log2(e)

// ---- pre-converted bf16 K/V (hi/lo split), row = 64 bf16 = 128 B ----
__device__ __align__(16) uint8_t gKhi[NELEM * 2];
__device__ __align__(16) uint8_t gKlo[NELEM * 2];
__device__ __align__(16) uint8_t gVhi[NELEM * 2];
__device__ __align__(16) uint8_t gVlo[NELEM * 2];

// ---- smem: 3 stages x 32KB (KHI|KLO|VHI|VLO, 8KB each, XOR-swizzled) ----
#define STAGE   32768
#define P_KHI   0
#define P_KLO   8192
#define P_VHI   16384
#define P_VLO   24576
#define SMEM_BYTES (3 * STAGE)          // 98304

__device__ __forceinline__ uint32_t smem_u32(const void* p) {
    uint32_t a;
    asm("{ .reg .u64 t; cvta.to.shared.u64 t, %1; cvt.u32.u64 %0, t; }" : "=r"(a) : "l"(p));
    return a;
}
__device__ __forceinline__ uint32_t swz(uint32_t b) { return b ^ ((b >> 3) & 0x70u); }
__device__ __forceinline__ float ex2(float x) {
    float r; asm("ex2.approx.f32 %0, %1;" : "=f"(r) : "f"(x)); return r;
}
__device__ __forceinline__ void cpa16(uint32_t dst, const void* src) {
    asm volatile("cp.async.cg.shared.global [%0], [%1], 16;" :: "r"(dst), "l"(src));
}
#define CP_COMMIT() asm volatile("cp.async.commit_group;" ::: "memory")
#define CP_WAIT(n)  asm volatile("cp.async.wait_group %0;" :: "n"(n) : "memory")

__device__ __forceinline__ void ldsm4(uint32_t r[4], uint32_t addr) {
    asm volatile("ldmatrix.sync.aligned.m8n8.x4.shared.b16 {%0,%1,%2,%3}, [%4];"
        : "=r"(r[0]), "=r"(r[1]), "=r"(r[2]), "=r"(r[3]) : "r"(addr));
}
__device__ __forceinline__ void ldsm4t(uint32_t r[4], uint32_t addr) {
    asm volatile("ldmatrix.sync.aligned.m8n8.x4.trans.shared.b16 {%0,%1,%2,%3}, [%4];"
        : "=r"(r[0]), "=r"(r[1]), "=r"(r[2]), "=r"(r[3]) : "r"(addr));
}
// NOTE: not volatile — lets ptxas interleave HMMA with softmax FMA/MUFU chains.
__device__ __forceinline__ void mma_bf16(float c[4], const uint32_t a[4],
                                         uint32_t b0, uint32_t b1) {
    asm("mma.sync.aligned.m16n8k16.row.col.f32.bf16.bf16.f32 "
        "{%0,%1,%2,%3}, {%4,%5,%6,%7}, {%8,%9}, {%0,%1,%2,%3};"
        : "+f"(c[0]), "+f"(c[1]), "+f"(c[2]), "+f"(c[3])
        : "r"(a[0]), "r"(a[1]), "r"(a[2]), "r"(a[3]), "r"(b0), "r"(b1));
}
__device__ __forceinline__ uint32_t packbf(float lo, float hi) {
    uint32_t r;
    asm("cvt.rn.bf16x2.f32 %0, %1, %2;" : "=r"(r) : "f"(hi), "f"(lo));
    return r;
}
__device__ __forceinline__ void split2(float x, float y, uint32_t& h, uint32_t& l) {
    h = packbf(x, y);
    float hx = __uint_as_float(h << 16);
    float hy = __uint_as_float(h & 0xffff0000u);
    l = packbf(x - hx, y - hy);
}

// ================= pre-pass: K,V fp32 -> bf16 hi/lo =================
__global__ __launch_bounds__(256)
void prep_kernel(const float* __restrict__ Kg, const float* __restrict__ Vg)
{
    const int i = blockIdx.x * 256 + threadIdx.x;      // per float4
    const int t = blockIdx.y;                          // 0=K 1=V
    const float4* src = (t == 0) ? (const float4*)Kg : (const float4*)Vg;
    uint2* hi = (t == 0) ? (uint2*)gKhi : (uint2*)gVhi;
    uint2* lo = (t == 0) ? (uint2*)gKlo : (uint2*)gVlo;

    float4 v = src[i];
    uint2 h, l;
    split2(v.x, v.y, h.x, l.x);
    split2(v.z, v.w, h.y, l.y);
    hi[i] = h;
    lo[i] = l;
}

// ================= main attention kernel =================
__global__ __launch_bounds__(NTHR, 1)
void fattn_mma_kernel(float* __restrict__ Og, const float* __restrict__ Qg)
{
    extern __shared__ __align__(1024) uint8_t smem[];
    const uint32_t sb = smem_u32(smem);

    const int tid  = threadIdx.x;
    const int w    = tid >> 5;
    const int lane = tid & 31;
    const int lr   = lane & 15;
    const int lc   = (lane >> 4) << 3;
    const int quad = lane & 3;

    const int qt = (gridDim.x - 1) - blockIdx.x;   // heavy tiles first
    const int bh = blockIdx.y;
    const size_t rowbase = (size_t)bh * SEQ;       // 128B-row index base

    const int n_kv = 2 * qt + 2;

    // tile issuer: one 32KB stage per kv tile (KHI|KLO|VHI|VLO)
    auto issue_tile = [&](int kt, uint32_t stg) {
        const size_t tb = (rowbase + (size_t)kt * BN) * 128;
        const uint8_t* kh = gKhi + tb;  const uint8_t* kl = gKlo + tb;
        const uint8_t* vh = gVhi + tb;  const uint8_t* vl = gVlo + tb;
        #pragma unroll
        for (int j = 0; j < 2; j++) {
            uint32_t idx = (uint32_t)(tid + j * NTHR);
            uint32_t off = idx << 4;
            uint32_t so  = sb + stg + swz(off);
            cpa16(so + P_KHI, kh + off);
            cpa16(so + P_KLO, kl + off);
            cpa16(so + P_VHI, vh + off);
            cpa16(so + P_VLO, vl + off);
        }
        CP_COMMIT();
    };

    issue_tile(0, 0);                   // stage 0 in flight

    // ---- Q: load fp32, scale+split, stage in stage-1 region (hi|lo 16KB each) ----
    {
        const float* Qb = Qg + (rowbase + (size_t)qt * BM) * DH;
        #pragma unroll
        for (int it = 0; it < 8; it++) {
            int i  = tid + it * NTHR;
            int r  = i >> 4;
            int c4 = (i & 15) << 2;
            float4 v = *(const float4*)(Qb + r * DH + c4);
            v.x *= QSCALE; v.y *= QSCALE; v.z *= QSCALE; v.w *= QSCALE;
            uint2 h, l;
            split2(v.x, v.y, h.x, l.x);
            split2(v.z, v.w, h.y, l.y);
            uint32_t off = swz((uint32_t)(r * 128 + c4 * 2));
            *(uint2*)(smem + STAGE + off)         = h;
            *(uint2*)(smem + STAGE + 16384 + off) = l;
        }
    }
    __syncthreads();

    uint32_t qh[4][4], ql[4][4];
    {
        uint32_t rowb = (uint32_t)((w * 16 + lr) * 128);
        #pragma unroll
        for (int ks = 0; ks < 4; ks++) {
            uint32_t a = sb + STAGE + swz(rowb + (uint32_t)((ks * 16 + lc) * 2));
            ldsm4(qh[ks], a);
            ldsm4(ql[ks], a + 16384);
        }
    }
    __syncthreads();                    // stage-1 region free
    issue_tile(1, STAGE);

    float o[8][4];
    #pragma unroll
    for (int n = 0; n < 8; n++)
        #pragma unroll
        for (int j = 0; j < 4; j++) o[n][j] = 0.f;
    float m0 = -1e30f, m1 = -1e30f, l0 = 0.f, l1 = 0.f;

    const int qg0 = qt * BM + w * 16 + (lane >> 2);

    // ---- S-GEMM helper (3-pass bf16) ----
    auto s_gemm = [&](float s[8][4], uint32_t stg) {
        #pragma unroll
        for (int n = 0; n < 8; n++)
            #pragma unroll
            for (int j = 0; j < 4; j++) s[n][j] = 0.f;
        #pragma unroll
        for (int ks = 0; ks < 4; ks++) {
            #pragma unroll
            for (int kg = 0; kg < 4; kg++) {
                uint32_t addr = stg + swz((uint32_t)((kg * 16 + lr) * 128)
                                          + (uint32_t)((ks * 16 + lc) * 2));
                uint32_t bhf[4], blf[4];
                ldsm4(bhf, addr + P_KHI);
                mma_bf16(s[2*kg],   qh[ks], bhf[0], bhf[2]);
                mma_bf16(s[2*kg+1], qh[ks], bhf[1], bhf[3]);
                mma_bf16(s[2*kg],   ql[ks], bhf[0], bhf[2]);
                mma_bf16(s[2*kg+1], ql[ks], bhf[1], bhf[3]);
                ldsm4(blf, addr + P_KLO);
                mma_bf16(s[2*kg],   qh[ks], blf[0], blf[2]);
                mma_bf16(s[2*kg+1], qh[ks], blf[1], blf[3]);
            }
        }
    };

    // ---- prolog: S(0) ----
    float s[8][4];
    CP_WAIT(1);                         // tile 0 resident (tile 1 may be pending)
    __syncthreads();
    s_gemm(s, sb);                      // stage 0

    for (int kt = 0; kt < n_kv; kt++) {
        const uint32_t stg_cur = sb + (uint32_t)(kt % 3) * STAGE;
        const bool have_next = (kt + 1 < n_kv);

        // ---- S(kt+1): independent tensor work interleaved with softmax(kt) ----
        float s_next[8][4];
        if (have_next) {
            CP_WAIT(0);                 // tile kt+1 resident (issued >=1 iter ago)
            __syncthreads();            // all warps done with stage (kt+2)%3 (PV kt-1)
            if (kt + 2 < n_kv) issue_tile(kt + 2, (uint32_t)((kt + 2) % 3) * STAGE);
            s_gemm(s_next, sb + (uint32_t)((kt + 1) % 3) * STAGE);
        }

        // ---- causal mask (diagonal tiles only) ----
        if (kt >= 2 * qt) {
            #pragma unroll
            for (int n = 0; n < 8; n++) {
                int kb = kt * BN + n * 8 + quad * 2;
                if (kb     > qg0)     s[n][0] = -1e30f;
                if (kb + 1 > qg0)     s[n][1] = -1e30f;
                if (kb     > qg0 + 8) s[n][2] = -1e30f;
                if (kb + 1 > qg0 + 8) s[n][3] = -1e30f;
            }
        }

        // ---- online softmax (log2 domain) ----
        float mx0 = s[0][0], mx1 = s[0][2];
        #pragma unroll
        for (int n = 0; n < 8; n++) {
            mx0 = fmaxf(mx0, fmaxf(s[n][0], s[n][1]));
            mx1 = fmaxf(mx1, fmaxf(s[n][2], s[n][3]));
        }
        mx0 = fmaxf(mx0, __shfl_xor_sync(0xffffffffu, mx0, 1));
        mx0 = fmaxf(mx0, __shfl_xor_sync(0xffffffffu, mx0, 2));
        mx1 = fmaxf(mx1, __shfl_xor_sync(0xffffffffu, mx1, 1));
        mx1 = fmaxf(mx1, __shfl_xor_sync(0xffffffffu, mx1, 2));

        float mn0 = fmaxf(m0, mx0), mn1 = fmaxf(m1, mx1);
        float a0 = ex2(m0 - mn0), a1 = ex2(m1 - mn1);
        m0 = mn0; m1 = mn1;

        float rs0 = 0.f, rs1 = 0.f;
        #pragma unroll
        for (int n = 0; n < 8; n++) {
            s[n][0] = ex2(s[n][0] - m0); rs0 += s[n][0];
            s[n][1] = ex2(s[n][1] - m0); rs0 += s[n][1];
            s[n][2] = ex2(s[n][2] - m1); rs1 += s[n][2];
            s[n][3] = ex2(s[n][3] - m1); rs1 += s[n][3];
        }
        rs0 += __shfl_xor_sync(0xffffffffu, rs0, 1);
        rs0 += __shfl_xor_sync(0xffffffffu, rs0, 2);
        rs1 += __shfl_xor_sync(0xffffffffu, rs1, 1);
        rs1 += __shfl_xor_sync(0xffffffffu, rs1, 2);
        l0 = l0 * a0 + rs0;
        l1 = l1 * a1 + rs1;

        #pragma unroll
        for (int n = 0; n < 8; n++) {
            o[n][0] *= a0; o[n][1] *= a0;
            o[n][2] *= a1; o[n][3] *= a1;
        }

        // ---- P -> A-fragments (hi + residual), register-only ----
        uint32_t pa[4][4], pl[4][4];
        #pragma unroll
        for (int j = 0; j < 4; j++) {
            split2(s[2*j][0],   s[2*j][1],   pa[j][0], pl[j][0]);
            split2(s[2*j][2],   s[2*j][3],   pa[j][1], pl[j][1]);
            split2(s[2*j+1][0], s[2*j+1][1], pa[j][2], pl[j][2]);
            split2(s[2*j+1][2], s[2*j+1][3], pa[j][3], pl[j][3]);
        }

        // ---- O += Phi.Vhi + Plo.Vhi + Phi.Vlo ----
        #pragma unroll
        for (int ks = 0; ks < 4; ks++) {
            #pragma unroll
            for (int dg = 0; dg < 4; dg++) {
                uint32_t addr = stg_cur + swz((uint32_t)((ks * 16 + lr) * 128)
                                              + (uint32_t)((dg * 16 + lc) * 2));
                uint32_t vhf[4], vlf[4];
                ldsm4t(vhf, addr + P_VHI);
                mma_bf16(o[2*dg],   pa[ks], vhf[0], vhf[1]);
                mma_bf16(o[2*dg+1], pa[ks], vhf[2], vhf[3]);
                mma_bf16(o[2*dg],   pl[ks], vhf[0], vhf[1]);
                mma_bf16(o[2*dg+1], pl[ks], vhf[2], vhf[3]);
                ldsm4t(vlf, addr + P_VLO);
                mma_bf16(o[2*dg],   pa[ks], vlf[0], vlf[1]);
                mma_bf16(o[2*dg+1], pa[ks], vlf[2], vlf[3]);
            }
        }

        if (have_next) {
            #pragma unroll
            for (int n = 0; n < 8; n++)
                #pragma unroll
                for (int j = 0; j < 4; j++) s[n][j] = s_next[n][j];
        }
    }

    // ---- epilogue ----
    float inv0 = 1.0f / l0, inv1 = 1.0f / l1;
    float* Orow0 = Og + (rowbase + qg0) * DH;
    float* Orow1 = Orow0 + 8 * DH;
    #pragma unroll
    for (int n = 0; n < 8; n++) {
        int d = n * 8 + quad * 2;
        *(float2*)(Orow0 + d) = make_float2(o[n][0] * inv0, o[n][1] * inv0);
        *(float2*)(Orow1 + d) = make_float2(o[n][2] * inv1, o[n][3] * inv1);
    }
}

extern "C" void kernel_launch(void* const* d_in, const int* in_sizes, int n_in,
                              void* d_out, int out_size)
{
    const float* Q = (const float*)d_in[0];
    const float* K = (const float*)d_in[1];
    const float* V = (const float*)d_in[2];
    float* O = (float*)d_out;

    dim3 pgrid(NELEM / 4 / 256, 2);     // (4096, 2): K and V
    prep_kernel<<<pgrid, 256>>>(K, V);

    cudaFuncSetAttribute(fattn_mma_kernel,
                         cudaFuncAttributeMaxDynamicSharedMemorySize, SMEM_BYTES);
    dim3 grid(SEQ / BM, BHN);           // (16, 32)
    fattn_mma_kernel<<<grid, NTHR, SMEM_BYTES>>>(O, Q);
}

// round 7
// speedup vs baseline: 1.1016x; 1.1013x over previous
#include <cuda_runtime.h>
#include <cstdint>

// B=2,H=16,S=2048,D=64 causal attention, fp32 in/out.
#define BHN   32
#define SEQ   2048
#define DH    64
#define BM    64                        // q rows per CTA (4 warps x 16)
#define BN    64
#define NTHR  128
#define NELEM (BHN * SEQ * DH)          // 4,194,304

#define QSCALE 0.18033688f              // 0.125 * log2(e)

// ---- pre-converted bf16 K/V (hi/lo split), row = 64 bf16 = 128 B ----
__device__ __align__(16) uint8_t gKhi[NELEM * 2];
__device__ __align__(16) uint8_t gKlo[NELEM * 2];
__device__ __align__(16) uint8_t gVhi[NELEM * 2];
__device__ __align__(16) uint8_t gVlo[NELEM * 2];

// ---- smem: 3 stages x 32KB (KHI|KLO|VHI|VLO, 8KB each, XOR-swizzled) ----
#define STAGE   32768
#define P_KHI   0
#define P_KLO   8192
#define P_VHI   16384
#define P_VLO   24576
#define SMEM_BYTES (3 * STAGE)          // 98304 -> 2 CTAs/SM

__device__ __forceinline__ uint32_t smem_u32(const void* p) {
    uint32_t a;
    asm("{ .reg .u64 t; cvta.to.shared.u64 t, %1; cvt.u32.u64 %0, t; }" : "=r"(a) : "l"(p));
    return a;
}
__device__ __forceinline__ uint32_t swz(uint32_t b) { return b ^ ((b >> 3) & 0x70u); }
__device__ __forceinline__ float ex2(float x) {
    float r; asm("ex2.approx.f32 %0, %1;" : "=f"(r) : "f"(x)); return r;
}
__device__ __forceinline__ void cpa16(uint32_t dst, const void* src) {
    asm volatile("cp.async.cg.shared.global [%0], [%1], 16;" :: "r"(dst), "l"(src));
}
#define CP_COMMIT() asm volatile("cp.async.commit_group;" ::: "memory")
#define CP_WAIT(n)  asm volatile("cp.async.wait_group %0;" :: "n"(n) : "memory")

__device__ __forceinline__ void ldsm4(uint32_t r[4], uint32_t addr) {
    asm volatile("ldmatrix.sync.aligned.m8n8.x4.shared.b16 {%0,%1,%2,%3}, [%4];"
        : "=r"(r[0]), "=r"(r[1]), "=r"(r[2]), "=r"(r[3]) : "r"(addr));
}
__device__ __forceinline__ void ldsm4t(uint32_t r[4], uint32_t addr) {
    asm volatile("ldmatrix.sync.aligned.m8n8.x4.trans.shared.b16 {%0,%1,%2,%3}, [%4];"
        : "=r"(r[0]), "=r"(r[1]), "=r"(r[2]), "=r"(r[3]) : "r"(addr));
}
// not volatile: lets ptxas schedule HMMA around FMA/MUFU chains
__device__ __forceinline__ void mma_bf16(float c[4], const uint32_t a[4],
                                         uint32_t b0, uint32_t b1) {
    asm("mma.sync.aligned.m16n8k16.row.col.f32.bf16.bf16.f32 "
        "{%0,%1,%2,%3}, {%4,%5,%6,%7}, {%8,%9}, {%0,%1,%2,%3};"
        : "+f"(c[0]), "+f"(c[1]), "+f"(c[2]), "+f"(c[3])
        : "r"(a[0]), "r"(a[1]), "r"(a[2]), "r"(a[3]), "r"(b0), "r"(b1));
}
__device__ __forceinline__ uint32_t packbf(float lo, float hi) {
    uint32_t r;
    asm("cvt.rn.bf16x2.f32 %0, %1, %2;" : "=r"(r) : "f"(hi), "f"(lo));
    return r;
}
__device__ __forceinline__ void split2(float x, float y, uint32_t& h, uint32_t& l) {
    h = packbf(x, y);
    float hx = __uint_as_float(h << 16);
    float hy = __uint_as_float(h & 0xffff0000u);
    l = packbf(x - hx, y - hy);
}

// ================= pre-pass: K,V fp32 -> bf16 hi/lo =================
__global__ __launch_bounds__(256)
void prep_kernel(const float* __restrict__ Kg, const float* __restrict__ Vg)
{
    const int i = blockIdx.x * 256 + threadIdx.x;      // per float4
    const int t = blockIdx.y;                          // 0=K 1=V
    const float4* src = (t == 0) ? (const float4*)Kg : (const float4*)Vg;
    uint2* hi = (t == 0) ? (uint2*)gKhi : (uint2*)gVhi;
    uint2* lo = (t == 0) ? (uint2*)gKlo : (uint2*)gVlo;

    float4 v = src[i];
    uint2 h, l;
    split2(v.x, v.y, h.x, l.x);
    split2(v.z, v.w, h.y, l.y);
    hi[i] = h;
    lo[i] = l;
}

// ================= main attention kernel =================
__global__ __launch_bounds__(NTHR)
void fattn_mma_kernel(float* __restrict__ Og, const float* __restrict__ Qg)
{
    extern __shared__ __align__(1024) uint8_t smem[];
    const uint32_t sb = smem_u32(smem);

    const int tid  = threadIdx.x;
    const int w    = tid >> 5;           // 0..3
    const int lane = tid & 31;
    const int lr   = lane & 15;
    const int lc   = (lane >> 4) << 3;
    const int quad = lane & 3;

    const int qt = (gridDim.x - 1) - blockIdx.x;   // heavy tiles first
    const int bh = blockIdx.y;
    const size_t rowbase = (size_t)bh * SEQ;       // 128B-row index base

    const int n_kv = qt + 1;                       // kv tiles 0..qt (BM == BN)

    // tile issuer: one 32KB stage (KHI|KLO|VHI|VLO); 16 cp.async per thread
    auto issue_tile = [&](int kt, uint32_t stg) {
        const size_t tb = (rowbase + (size_t)kt * BN) * 128;
        const uint8_t* kh = gKhi + tb;  const uint8_t* kl = gKlo + tb;
        const uint8_t* vh = gVhi + tb;  const uint8_t* vl = gVlo + tb;
        #pragma unroll
        for (int j = 0; j < 4; j++) {
            uint32_t idx = (uint32_t)(tid + j * NTHR);
            uint32_t off = idx << 4;                 // 0..8176
            uint32_t so  = sb + stg + swz(off);
            cpa16(so + P_KHI, kh + off);
            cpa16(so + P_KLO, kl + off);
            cpa16(so + P_VHI, vh + off);
            cpa16(so + P_VLO, vl + off);
        }
        CP_COMMIT();
    };

    issue_tile(0, 0);                   // stage 0 in flight

    // ---- Q: load fp32, scale+split, stage in stage-1 region (hi|lo 8KB each) ----
    {
        const float* Qb = Qg + (rowbase + (size_t)qt * BM) * DH;
        #pragma unroll
        for (int it = 0; it < 8; it++) {
            int i  = tid + it * NTHR;   // 0..1023 float4
            int r  = i >> 4;
            int c4 = (i & 15) << 2;
            float4 v = *(const float4*)(Qb + r * DH + c4);
            v.x *= QSCALE; v.y *= QSCALE; v.z *= QSCALE; v.w *= QSCALE;
            uint2 h, l;
            split2(v.x, v.y, h.x, l.x);
            split2(v.z, v.w, h.y, l.y);
            uint32_t off = swz((uint32_t)(r * 128 + c4 * 2));
            *(uint2*)(smem + STAGE + off)        = h;
            *(uint2*)(smem + STAGE + 8192 + off) = l;
        }
    }
    __syncthreads();

    uint32_t qh[4][4], ql[4][4];
    {
        uint32_t rowb = (uint32_t)((w * 16 + lr) * 128);
        #pragma unroll
        for (int ks = 0; ks < 4; ks++) {
            uint32_t a = sb + STAGE + swz(rowb + (uint32_t)((ks * 16 + lc) * 2));
            ldsm4(qh[ks], a);
            ldsm4(ql[ks], a + 8192);
        }
    }
    __syncthreads();                    // stage-1 region free
    if (n_kv > 1) issue_tile(1, STAGE);

    float o[8][4];
    #pragma unroll
    for (int n = 0; n < 8; n++)
        #pragma unroll
        for (int j = 0; j < 4; j++) o[n][j] = 0.f;
    float m0 = -1e30f, m1 = -1e30f, l0 = 0.f, l1 = 0.f;

    const int qg0 = qt * BM + w * 16 + (lane >> 2);

    for (int kt = 0; kt < n_kv; kt++) {
        if (kt + 1 < n_kv) { CP_WAIT(1); } else { CP_WAIT(0); }   // tile kt resident
        __syncthreads();                // prev stage fully consumed by all warps
        if (kt + 2 < n_kv) issue_tile(kt + 2, (uint32_t)((kt + 2) % 3) * STAGE);

        const uint32_t stg = sb + (uint32_t)(kt % 3) * STAGE;

        // ---- S = Qhi.Khi + Qlo.Khi + Qhi.Klo ----
        float s[8][4];
        #pragma unroll
        for (int n = 0; n < 8; n++)
            #pragma unroll
            for (int j = 0; j < 4; j++) s[n][j] = 0.f;

        #pragma unroll
        for (int ks = 0; ks < 4; ks++) {
            #pragma unroll
            for (int kg = 0; kg < 4; kg++) {
                uint32_t addr = stg + swz((uint32_t)((kg * 16 + lr) * 128)
                                          + (uint32_t)((ks * 16 + lc) * 2));
                uint32_t bhf[4], blf[4];
                ldsm4(bhf, addr + P_KHI);
                mma_bf16(s[2*kg],   qh[ks], bhf[0], bhf[2]);
                mma_bf16(s[2*kg+1], qh[ks], bhf[1], bhf[3]);
                mma_bf16(s[2*kg],   ql[ks], bhf[0], bhf[2]);
                mma_bf16(s[2*kg+1], ql[ks], bhf[1], bhf[3]);
                ldsm4(blf, addr + P_KLO);
                mma_bf16(s[2*kg],   qh[ks], blf[0], blf[2]);
                mma_bf16(s[2*kg+1], qh[ks], blf[1], blf[3]);
            }
        }

        // ---- causal mask (diagonal tile only) ----
        if (kt == qt) {
            #pragma unroll
            for (int n = 0; n < 8; n++) {
                int kb = kt * BN + n * 8 + quad * 2;
                if (kb     > qg0)     s[n][0] = -1e30f;
                if (kb + 1 > qg0)     s[n][1] = -1e30f;
                if (kb     > qg0 + 8) s[n][2] = -1e30f;
                if (kb + 1 > qg0 + 8) s[n][3] = -1e30f;
            }
        }

        // ---- online softmax (log2 domain) ----
        float mx0 = s[0][0], mx1 = s[0][2];
        #pragma unroll
        for (int n = 0; n < 8; n++) {
            mx0 = fmaxf(mx0, fmaxf(s[n][0], s[n][1]));
            mx1 = fmaxf(mx1, fmaxf(s[n][2], s[n][3]));
        }
        mx0 = fmaxf(mx0, __shfl_xor_sync(0xffffffffu, mx0, 1));
        mx0 = fmaxf(mx0, __shfl_xor_sync(0xffffffffu, mx0, 2));
        mx1 = fmaxf(mx1, __shfl_xor_sync(0xffffffffu, mx1, 1));
        mx1 = fmaxf(mx1, __shfl_xor_sync(0xffffffffu, mx1, 2));

        float mn0 = fmaxf(m0, mx0), mn1 = fmaxf(m1, mx1);
        float a0 = ex2(m0 - mn0), a1 = ex2(m1 - mn1);
        m0 = mn0; m1 = mn1;

        float rs0 = 0.f, rs1 = 0.f;
        #pragma unroll
        for (int n = 0; n < 8; n++) {
            s[n][0] = ex2(s[n][0] - m0); rs0 += s[n][0];
            s[n][1] = ex2(s[n][1] - m0); rs0 += s[n][1];
            s[n][2] = ex2(s[n][2] - m1); rs1 += s[n][2];
            s[n][3] = ex2(s[n][3] - m1); rs1 += s[n][3];
        }
        rs0 += __shfl_xor_sync(0xffffffffu, rs0, 1);
        rs0 += __shfl_xor_sync(0xffffffffu, rs0, 2);
        rs1 += __shfl_xor_sync(0xffffffffu, rs1, 1);
        rs1 += __shfl_xor_sync(0xffffffffu, rs1, 2);
        l0 = l0 * a0 + rs0;
        l1 = l1 * a1 + rs1;

        #pragma unroll
        for (int n = 0; n < 8; n++) {
            o[n][0] *= a0; o[n][1] *= a0;
            o[n][2] *= a1; o[n][3] *= a1;
        }

        // ---- P -> A-fragments (hi + residual), register-only ----
        uint32_t pa[4][4], pl[4][4];
        #pragma unroll
        for (int j = 0; j < 4; j++) {
            split2(s[2*j][0],   s[2*j][1],   pa[j][0], pl[j][0]);
            split2(s[2*j][2],   s[2*j][3],   pa[j][1], pl[j][1]);
            split2(s[2*j+1][0], s[2*j+1][1], pa[j][2], pl[j][2]);
            split2(s[2*j+1][2], s[2*j+1][3], pa[j][3], pl[j][3]);
        }

        // ---- O += Phi.Vhi + Plo.Vhi + Phi.Vlo ----
        #pragma unroll
        for (int ks = 0; ks < 4; ks++) {
            #pragma unroll
            for (int dg = 0; dg < 4; dg++) {
                uint32_t addr = stg + swz((uint32_t)((ks * 16 + lr) * 128)
                                          + (uint32_t)((dg * 16 + lc) * 2));
                uint32_t vhf[4], vlf[4];
                ldsm4t(vhf, addr + P_VHI);
                mma_bf16(o[2*dg],   pa[ks], vhf[0], vhf[1]);
                mma_bf16(o[2*dg+1], pa[ks], vhf[2], vhf[3]);
                mma_bf16(o[2*dg],   pl[ks], vhf[0], vhf[1]);
                mma_bf16(o[2*dg+1], pl[ks], vhf[2], vhf[3]);
                ldsm4t(vlf, addr + P_VLO);
                mma_bf16(o[2*dg],   pa[ks], vlf[0], vlf[1]);
                mma_bf16(o[2*dg+1], pa[ks], vlf[2], vlf[3]);
            }
        }
    }

    // ---- epilogue ----
    float inv0 = 1.0f / l0, inv1 = 1.0f / l1;
    float* Orow0 = Og + (rowbase + qg0) * DH;
    float* Orow1 = Orow0 + 8 * DH;
    #pragma unroll
    for (int n = 0; n < 8; n++) {
        int d = n * 8 + quad * 2;
        *(float2*)(Orow0 + d) = make_float2(o[n][0] * inv0, o[n][1] * inv0);
        *(float2*)(Orow1 + d) = make_float2(o[n][2] * inv1, o[n][3] * inv1);
    }
}

extern "C" void kernel_launch(void* const* d_in, const int* in_sizes, int n_in,
                              void* d_out, int out_size)
{
    const float* Q = (const float*)d_in[0];
    const float* K = (const float*)d_in[1];
    const float* V = (const float*)d_in[2];
    float* O = (float*)d_out;

    dim3 pgrid(NELEM / 4 / 256, 2);     // (4096, 2): K and V
    prep_kernel<<<pgrid, 256>>>(K, V);

    cudaFuncSetAttribute(fattn_mma_kernel,
                         cudaFuncAttributeMaxDynamicSharedMemorySize, SMEM_BYTES);
    dim3 grid(SEQ / BM, BHN);           // (32, 32)
    fattn_mma_kernel<<<grid, NTHR, SMEM_BYTES>>>(O, Q);
}

// round 8
// speedup vs baseline: 1.1266x; 1.0227x over previous
#include <cuda_runtime.h>
#include <cstdint>

// B=2,H=16,S=2048,D=64 causal attention, fp32 in/out.
#define BHN   32
#define SEQ   2048
#define DH    64
#define BM    64                        // q rows per CTA (4 warps x 16)
#define BN    64
#define NTHR  128
#define NELEM (BHN * SEQ * DH)          // 4,194,304

#define QSCALE 0.18033688f              // 0.125 * log2(e)

// ---- pre-converted bf16 K/V (hi/lo split), row = 64 bf16 = 128 B ----
__device__ __align__(16) uint8_t gKhi[NELEM * 2];
__device__ __align__(16) uint8_t gKlo[NELEM * 2];
__device__ __align__(16) uint8_t gVhi[NELEM * 2];
__device__ __align__(16) uint8_t gVlo[NELEM * 2];

// ---- smem: 2 stages x 32KB (KHI|KLO|VHI|VLO, 8KB each, XOR-swizzled) ----
#define STAGE   32768
#define P_KHI   0
#define P_KLO   8192
#define P_VHI   16384
#define P_VLO   24576
#define SMEM_BYTES (2 * STAGE)          // 65536 -> 3 CTAs/SM

__device__ __forceinline__ uint32_t smem_u32(const void* p) {
    uint32_t a;
    asm("{ .reg .u64 t; cvta.to.shared.u64 t, %1; cvt.u32.u64 %0, t; }" : "=r"(a) : "l"(p));
    return a;
}
__device__ __forceinline__ uint32_t swz(uint32_t b) { return b ^ ((b >> 3) & 0x70u); }
__device__ __forceinline__ float ex2(float x) {
    float r; asm("ex2.approx.f32 %0, %1;" : "=f"(r) : "f"(x)); return r;
}
__device__ __forceinline__ void cpa16(uint32_t dst, const void* src) {
    asm volatile("cp.async.cg.shared.global [%0], [%1], 16;" :: "r"(dst), "l"(src));
}
#define CP_COMMIT() asm volatile("cp.async.commit_group;" ::: "memory")
#define CP_WAIT(n)  asm volatile("cp.async.wait_group %0;" :: "n"(n) : "memory")

__device__ __forceinline__ void ldsm4(uint32_t r[4], uint32_t addr) {
    asm volatile("ldmatrix.sync.aligned.m8n8.x4.shared.b16 {%0,%1,%2,%3}, [%4];"
        : "=r"(r[0]), "=r"(r[1]), "=r"(r[2]), "=r"(r[3]) : "r"(addr));
}
__device__ __forceinline__ void ldsm4t(uint32_t r[4], uint32_t addr) {
    asm volatile("ldmatrix.sync.aligned.m8n8.x4.trans.shared.b16 {%0,%1,%2,%3}, [%4];"
        : "=r"(r[0]), "=r"(r[1]), "=r"(r[2]), "=r"(r[3]) : "r"(addr));
}
// not volatile: lets ptxas schedule HMMA around FMA/MUFU chains
__device__ __forceinline__ void mma_bf16(float c[4], const uint32_t a[4],
                                         uint32_t b0, uint32_t b1) {
    asm("mma.sync.aligned.m16n8k16.row.col.f32.bf16.bf16.f32 "
        "{%0,%1,%2,%3}, {%4,%5,%6,%7}, {%8,%9}, {%0,%1,%2,%3};"
        : "+f"(c[0]), "+f"(c[1]), "+f"(c[2]), "+f"(c[3])
        : "r"(a[0]), "r"(a[1]), "r"(a[2]), "r"(a[3]), "r"(b0), "r"(b1));
}
__device__ __forceinline__ uint32_t packbf(float lo, float hi) {
    uint32_t r;
    asm("cvt.rn.bf16x2.f32 %0, %1, %2;" : "=r"(r) : "f"(hi), "f"(lo));
    return r;
}
__device__ __forceinline__ void split2(float x, float y, uint32_t& h, uint32_t& l) {
    h = packbf(x, y);
    float hx = __uint_as_float(h << 16);
    float hy = __uint_as_float(h & 0xffff0000u);
    l = packbf(x - hx, y - hy);
}

// ================= pre-pass: K,V fp32 -> bf16 hi/lo =================
__global__ __launch_bounds__(256)
void prep_kernel(const float* __restrict__ Kg, const float* __restrict__ Vg)
{
    const int i = blockIdx.x * 256 + threadIdx.x;      // per float4
    const int t = blockIdx.y;                          // 0=K 1=V
    const float4* src = (t == 0) ? (const float4*)Kg : (const float4*)Vg;
    uint2* hi = (t == 0) ? (uint2*)gKhi : (uint2*)gVhi;
    uint2* lo = (t == 0) ? (uint2*)gKlo : (uint2*)gVlo;

    float4 v = src[i];
    uint2 h, l;
    split2(v.x, v.y, h.x, l.x);
    split2(v.z, v.w, h.y, l.y);
    hi[i] = h;
    lo[i] = l;
}

// ================= main attention kernel =================
__global__ __launch_bounds__(NTHR, 3)
void fattn_mma_kernel(float* __restrict__ Og, const float* __restrict__ Qg)
{
    extern __shared__ __align__(1024) uint8_t smem[];
    const uint32_t sb = smem_u32(smem);

    const int tid  = threadIdx.x;
    const int w    = tid >> 5;           // 0..3
    const int lane = tid & 31;
    const int lr   = lane & 15;
    const int lc   = (lane >> 4) << 3;
    const int quad = lane & 3;

    const int qt = (gridDim.x - 1) - blockIdx.x;   // heavy tiles first
    const int bh = blockIdx.y;
    const size_t rowbase = (size_t)bh * SEQ;       // 128B-row index base

    const int n_kv = qt + 1;                       // kv tiles 0..qt (BM == BN)

    // tile issuer: one 32KB stage (KHI|KLO|VHI|VLO); 16 cp.async per thread
    auto issue_tile = [&](int kt, uint32_t stg) {
        const size_t tb = (rowbase + (size_t)kt * BN) * 128;
        const uint8_t* kh = gKhi + tb;  const uint8_t* kl = gKlo + tb;
        const uint8_t* vh = gVhi + tb;  const uint8_t* vl = gVlo + tb;
        #pragma unroll
        for (int j = 0; j < 4; j++) {
            uint32_t idx = (uint32_t)(tid + j * NTHR);
            uint32_t off = idx << 4;                 // 0..8176
            uint32_t so  = sb + stg + swz(off);
            cpa16(so + P_KHI, kh + off);
            cpa16(so + P_KLO, kl + off);
            cpa16(so + P_VHI, vh + off);
            cpa16(so + P_VLO, vl + off);
        }
        CP_COMMIT();
    };

    issue_tile(0, 0);                   // stage 0 in flight

    // ---- Q: load fp32, scale+split, stage in stage-1 region (hi|lo 8KB each) ----
    {
        const float* Qb = Qg + (rowbase + (size_t)qt * BM) * DH;
        #pragma unroll
        for (int it = 0; it < 8; it++) {
            int i  = tid + it * NTHR;   // 0..1023 float4
            int r  = i >> 4;
            int c4 = (i & 15) << 2;
            float4 v = *(const float4*)(Qb + r * DH + c4);
            v.x *= QSCALE; v.y *= QSCALE; v.z *= QSCALE; v.w *= QSCALE;
            uint2 h, l;
            split2(v.x, v.y, h.x, l.x);
            split2(v.z, v.w, h.y, l.y);
            uint32_t off = swz((uint32_t)(r * 128 + c4 * 2));
            *(uint2*)(smem + STAGE + off)        = h;
            *(uint2*)(smem + STAGE + 8192 + off) = l;
        }
    }
    __syncthreads();

    uint32_t qh[4][4], ql[4][4];
    {
        uint32_t rowb = (uint32_t)((w * 16 + lr) * 128);
        #pragma unroll
        for (int ks = 0; ks < 4; ks++) {
            uint32_t a = sb + STAGE + swz(rowb + (uint32_t)((ks * 16 + lc) * 2));
            ldsm4(qh[ks], a);
            ldsm4(ql[ks], a + 8192);
        }
    }

    float o[8][4];
    #pragma unroll
    for (int n = 0; n < 8; n++)
        #pragma unroll
        for (int j = 0; j < 4; j++) o[n][j] = 0.f;
    float m0 = -1e30f, m1 = -1e30f, l0 = 0.f, l1 = 0.f;

    const int qg0 = qt * BM + w * 16 + (lane >> 2);

    for (int kt = 0; kt < n_kv; kt++) {
        // guard the stage we are about to overwrite, then issue kt+1, then wait kt
        if (kt + 1 < n_kv) {
            __syncthreads();            // all warps done with stage (kt+1)%2
                                        // (iter 0: Q frags already extracted)
            issue_tile(kt + 1, (uint32_t)((kt + 1) & 1) * STAGE);
            CP_WAIT(1);                 // tile kt resident (kt+1 may be pending)
        } else {
            CP_WAIT(0);                 // last tile: everything resident
        }
        __syncthreads();                // cp.async writes visible to all warps

        const uint32_t stg = sb + (uint32_t)(kt & 1) * STAGE;

        // ---- S = Qhi.Khi + Qlo.Khi + Qhi.Klo ----
        float s[8][4];
        #pragma unroll
        for (int n = 0; n < 8; n++)
            #pragma unroll
            for (int j = 0; j < 4; j++) s[n][j] = 0.f;

        #pragma unroll
        for (int ks = 0; ks < 4; ks++) {
            #pragma unroll
            for (int kg = 0; kg < 4; kg++) {
                uint32_t addr = stg + swz((uint32_t)((kg * 16 + lr) * 128)
                                          + (uint32_t)((ks * 16 + lc) * 2));
                uint32_t bhf[4], blf[4];
                ldsm4(bhf, addr + P_KHI);
                mma_bf16(s[2*kg],   qh[ks], bhf[0], bhf[2]);
                mma_bf16(s[2*kg+1], qh[ks], bhf[1], bhf[3]);
                mma_bf16(s[2*kg],   ql[ks], bhf[0], bhf[2]);
                mma_bf16(s[2*kg+1], ql[ks], bhf[1], bhf[3]);
                ldsm4(blf, addr + P_KLO);
                mma_bf16(s[2*kg],   qh[ks], blf[0], blf[2]);
                mma_bf16(s[2*kg+1], qh[ks], blf[1], blf[3]);
            }
        }

        // ---- causal mask (diagonal tile only) ----
        if (kt == qt) {
            #pragma unroll
            for (int n = 0; n < 8; n++) {
                int kb = kt * BN + n * 8 + quad * 2;
                if (kb     > qg0)     s[n][0] = -1e30f;
                if (kb + 1 > qg0)     s[n][1] = -1e30f;
                if (kb     > qg0 + 8) s[n][2] = -1e30f;
                if (kb + 1 > qg0 + 8) s[n][3] = -1e30f;
            }
        }

        // ---- online softmax (log2 domain) ----
        float mx0 = s[0][0], mx1 = s[0][2];
        #pragma unroll
        for (int n = 0; n < 8; n++) {
            mx0 = fmaxf(mx0, fmaxf(s[n][0], s[n][1]));
            mx1 = fmaxf(mx1, fmaxf(s[n][2], s[n][3]));
        }
        mx0 = fmaxf(mx0, __shfl_xor_sync(0xffffffffu, mx0, 1));
        mx0 = fmaxf(mx0, __shfl_xor_sync(0xffffffffu, mx0, 2));
        mx1 = fmaxf(mx1, __shfl_xor_sync(0xffffffffu, mx1, 1));
        mx1 = fmaxf(mx1, __shfl_xor_sync(0xffffffffu, mx1, 2));

        float mn0 = fmaxf(m0, mx0), mn1 = fmaxf(m1, mx1);
        float a0 = ex2(m0 - mn0), a1 = ex2(m1 - mn1);
        m0 = mn0; m1 = mn1;

        float rs0 = 0.f, rs1 = 0.f;
        #pragma unroll
        for (int n = 0; n < 8; n++) {
            s[n][0] = ex2(s[n][0] - m0); rs0 += s[n][0];
            s[n][1] = ex2(s[n][1] - m0); rs0 += s[n][1];
            s[n][2] = ex2(s[n][2] - m1); rs1 += s[n][2];
            s[n][3] = ex2(s[n][3] - m1); rs1 += s[n][3];
        }
        rs0 += __shfl_xor_sync(0xffffffffu, rs0, 1);
        rs0 += __shfl_xor_sync(0xffffffffu, rs0, 2);
        rs1 += __shfl_xor_sync(0xffffffffu, rs1, 1);
        rs1 += __shfl_xor_sync(0xffffffffu, rs1, 2);
        l0 = l0 * a0 + rs0;
        l1 = l1 * a1 + rs1;

        #pragma unroll
        for (int n = 0; n < 8; n++) {
            o[n][0] *= a0; o[n][1] *= a0;
            o[n][2] *= a1; o[n][3] *= a1;
        }

        // ---- P -> A-fragments (hi + residual), register-only ----
        uint32_t pa[4][4], pl[4][4];
        #pragma unroll
        for (int j = 0; j < 4; j++) {
            split2(s[2*j][0],   s[2*j][1],   pa[j][0], pl[j][0]);
            split2(s[2*j][2],   s[2*j][3],   pa[j][1], pl[j][1]);
            split2(s[2*j+1][0], s[2*j+1][1], pa[j][2], pl[j][2]);
            split2(s[2*j+1][2], s[2*j+1][3], pa[j][3], pl[j][3]);
        }

        // ---- O += Phi.Vhi + Plo.Vhi + Phi.Vlo ----
        #pragma unroll
        for (int ks = 0; ks < 4; ks++) {
            #pragma unroll
            for (int dg = 0; dg < 4; dg++) {
                uint32_t addr = stg + swz((uint32_t)((ks * 16 + lr) * 128)
                                          + (uint32_t)((dg * 16 + lc) * 2));
                uint32_t vhf[4], vlf[4];
                ldsm4t(vhf, addr + P_VHI);
                mma_bf16(o[2*dg],   pa[ks], vhf[0], vhf[1]);
                mma_bf16(o[2*dg+1], pa[ks], vhf[2], vhf[3]);
                mma_bf16(o[2*dg],   pl[ks], vhf[0], vhf[1]);
                mma_bf16(o[2*dg+1], pl[ks], vhf[2], vhf[3]);
                ldsm4t(vlf, addr + P_VLO);
                mma_bf16(o[2*dg],   pa[ks], vlf[0], vlf[1]);
                mma_bf16(o[2*dg+1], pa[ks], vlf[2], vlf[3]);
            }
        }
    }

    // ---- epilogue ----
    float inv0 = 1.0f / l0, inv1 = 1.0f / l1;
    float* Orow0 = Og + (rowbase + qg0) * DH;
    float* Orow1 = Orow0 + 8 * DH;
    #pragma unroll
    for (int n = 0; n < 8; n++) {
        int d = n * 8 + quad * 2;
        *(float2*)(Orow0 + d) = make_float2(o[n][0] * inv0, o[n][1] * inv0);
        *(float2*)(Orow1 + d) = make_float2(o[n][2] * inv1, o[n][3] * inv1);
    }
}

extern "C" void kernel_launch(void* const* d_in, const int* in_sizes, int n_in,
                              void* d_out, int out_size)
{
    const float* Q = (const float*)d_in[0];
    const float* K = (const float*)d_in[1];
    const float* V = (const float*)d_in[2];
    float* O = (float*)d_out;

    dim3 pgrid(NELEM / 4 / 256, 2);     // (4096, 2): K and V
    prep_kernel<<<pgrid, 256>>>(K, V);

    cudaFuncSetAttribute(fattn_mma_kernel,
                         cudaFuncAttributeMaxDynamicSharedMemorySize, SMEM_BYTES);
    dim3 grid(SEQ / BM, BHN);           // (32, 32)
    fattn_mma_kernel<<<grid, NTHR, SMEM_BYTES>>>(O, Q);
}

// round 9
// speedup vs baseline: 1.4910x; 1.3234x over previous
#include <cuda_runtime.h>
#include <cuda_fp16.h>
#include <cstdint>

// B=2,H=16,S=2048,D=64 causal attention, fp32 in/out.
#define BHN   32
#define SEQ   2048
#define DH    64
#define BM    64                        // q rows per CTA (4 warps x 16)
#define BN    64
#define NTHR  128
#define NELEM (BHN * SEQ * DH)          // 4,194,304

#define QSCALE 0.18033688f              // 0.125 * log2(e)

// ---- pre-converted fp16 K/V (hi + residual), row = 64 fp16 = 128 B ----
__device__ __align__(16) uint8_t gKhi[NELEM * 2];
__device__ __align__(16) uint8_t gKlo[NELEM * 2];
__device__ __align__(16) uint8_t gVhi[NELEM * 2];
__device__ __align__(16) uint8_t gVlo[NELEM * 2];

// ---- smem: 2 stages x 32KB (KHI|KLO|VHI|VLO, 8KB each, XOR-swizzled) ----
#define STAGE   32768
#define P_KHI   0
#define P_KLO   8192
#define P_VHI   16384
#define P_VLO   24576
#define SMEM_BYTES (2 * STAGE)          // 65536 -> 3 CTAs/SM

__device__ __forceinline__ uint32_t smem_u32(const void* p) {
    uint32_t a;
    asm("{ .reg .u64 t; cvta.to.shared.u64 t, %1; cvt.u32.u64 %0, t; }" : "=r"(a) : "l"(p));
    return a;
}
__device__ __forceinline__ uint32_t swz(uint32_t b) { return b ^ ((b >> 3) & 0x70u); }
__device__ __forceinline__ float ex2(float x) {
    float r; asm("ex2.approx.f32 %0, %1;" : "=f"(r) : "f"(x)); return r;
}
__device__ __forceinline__ void cpa16(uint32_t dst, const void* src) {
    asm volatile("cp.async.cg.shared.global [%0], [%1], 16;" :: "r"(dst), "l"(src));
}
#define CP_COMMIT() asm volatile("cp.async.commit_group;" ::: "memory")
#define CP_WAIT(n)  asm volatile("cp.async.wait_group %0;" :: "n"(n) : "memory")

__device__ __forceinline__ void ldsm4(uint32_t r[4], uint32_t addr) {
    asm volatile("ldmatrix.sync.aligned.m8n8.x4.shared.b16 {%0,%1,%2,%3}, [%4];"
        : "=r"(r[0]), "=r"(r[1]), "=r"(r[2]), "=r"(r[3]) : "r"(addr));
}
__device__ __forceinline__ void ldsm4t(uint32_t r[4], uint32_t addr) {
    asm volatile("ldmatrix.sync.aligned.m8n8.x4.trans.shared.b16 {%0,%1,%2,%3}, [%4];"
        : "=r"(r[0]), "=r"(r[1]), "=r"(r[2]), "=r"(r[3]) : "r"(addr));
}
// not volatile: lets ptxas schedule HMMA around FMA/MUFU chains
__device__ __forceinline__ void mma_f16(float c[4], const uint32_t a[4],
                                        uint32_t b0, uint32_t b1) {
    asm("mma.sync.aligned.m16n8k16.row.col.f32.f16.f16.f32 "
        "{%0,%1,%2,%3}, {%4,%5,%6,%7}, {%8,%9}, {%0,%1,%2,%3};"
        : "+f"(c[0]), "+f"(c[1]), "+f"(c[2]), "+f"(c[3])
        : "r"(a[0]), "r"(a[1]), "r"(a[2]), "r"(a[3]), "r"(b0), "r"(b1));
}
// pack two floats into fp16x2 (first arg -> low half / smaller col index)
__device__ __forceinline__ uint32_t packh(float lo, float hi) {
    uint32_t r;
    asm("cvt.rn.f16x2.f32 %0, %1, %2;" : "=r"(r) : "f"(hi), "f"(lo));
    return r;
}
// split (x,y) into fp16x2 hi part and fp16x2 residual
__device__ __forceinline__ void split2h(float x, float y, uint32_t& h, uint32_t& l) {
    h = packh(x, y);
    __half2 hh = *reinterpret_cast<__half2*>(&h);
    float hx = __half2float(__low2half(hh));
    float hy = __half2float(__high2half(hh));
    l = packh(x - hx, y - hy);
}

// ================= pre-pass: K,V fp32 -> fp16 hi/lo =================
__global__ __launch_bounds__(256)
void prep_kernel(const float* __restrict__ Kg, const float* __restrict__ Vg)
{
    const int i = blockIdx.x * 256 + threadIdx.x;      // per float4
    const int t = blockIdx.y;                          // 0=K 1=V
    const float4* src = (t == 0) ? (const float4*)Kg : (const float4*)Vg;
    uint2* hi = (t == 0) ? (uint2*)gKhi : (uint2*)gVhi;
    uint2* lo = (t == 0) ? (uint2*)gKlo : (uint2*)gVlo;

    float4 v = src[i];
    uint2 h, l;
    split2h(v.x, v.y, h.x, l.x);
    split2h(v.z, v.w, h.y, l.y);
    hi[i] = h;
    lo[i] = l;
}

// ================= main attention kernel =================
__global__ __launch_bounds__(NTHR, 3)
void fattn_mma_kernel(float* __restrict__ Og, const float* __restrict__ Qg)
{
    extern __shared__ __align__(1024) uint8_t smem[];
    const uint32_t sb = smem_u32(smem);

    const int tid  = threadIdx.x;
    const int w    = tid >> 5;           // 0..3
    const int lane = tid & 31;
    const int lr   = lane & 15;
    const int lc   = (lane >> 4) << 3;
    const int quad = lane & 3;

    const int qt = (gridDim.x - 1) - blockIdx.x;   // heavy tiles first
    const int bh = blockIdx.y;
    const size_t rowbase = (size_t)bh * SEQ;       // 128B-row index base

    const int n_kv = qt + 1;                       // kv tiles 0..qt (BM == BN)

    // tile issuer: one 32KB stage (KHI|KLO|VHI|VLO); 16 cp.async per thread
    auto issue_tile = [&](int kt, uint32_t stg) {
        const size_t tb = (rowbase + (size_t)kt * BN) * 128;
        const uint8_t* kh = gKhi + tb;  const uint8_t* kl = gKlo + tb;
        const uint8_t* vh = gVhi + tb;  const uint8_t* vl = gVlo + tb;
        #pragma unroll
        for (int j = 0; j < 4; j++) {
            uint32_t idx = (uint32_t)(tid + j * NTHR);
            uint32_t off = idx << 4;                 // 0..8176
            uint32_t so  = sb + stg + swz(off);
            cpa16(so + P_KHI, kh + off);
            cpa16(so + P_KLO, kl + off);
            cpa16(so + P_VHI, vh + off);
            cpa16(so + P_VLO, vl + off);
        }
        CP_COMMIT();
    };

    issue_tile(0, 0);                   // stage 0 in flight

    // ---- Q: load fp32, scale, fp16 pack, stage in stage-1 region (8KB) ----
    {
        const float* Qb = Qg + (rowbase + (size_t)qt * BM) * DH;
        #pragma unroll
        for (int it = 0; it < 8; it++) {
            int i  = tid + it * NTHR;   // 0..1023 float4
            int r  = i >> 4;
            int c4 = (i & 15) << 2;
            float4 v = *(const float4*)(Qb + r * DH + c4);
            uint2 h;
            h.x = packh(v.x * QSCALE, v.y * QSCALE);
            h.y = packh(v.z * QSCALE, v.w * QSCALE);
            *(uint2*)(smem + STAGE + swz((uint32_t)(r * 128 + c4 * 2))) = h;
        }
    }
    __syncthreads();

    uint32_t qh[4][4];
    {
        uint32_t rowb = (uint32_t)((w * 16 + lr) * 128);
        #pragma unroll
        for (int ks = 0; ks < 4; ks++)
            ldsm4(qh[ks], sb + STAGE + swz(rowb + (uint32_t)((ks * 16 + lc) * 2)));
    }

    float o[8][4];
    #pragma unroll
    for (int n = 0; n < 8; n++)
        #pragma unroll
        for (int j = 0; j < 4; j++) o[n][j] = 0.f;
    float m0 = -1e30f, m1 = -1e30f, l0 = 0.f, l1 = 0.f;

    const int qg0 = qt * BM + w * 16 + (lane >> 2);

    for (int kt = 0; kt < n_kv; kt++) {
        // guard the stage we are about to overwrite, then issue kt+1, then wait kt
        if (kt + 1 < n_kv) {
            __syncthreads();            // all warps done with stage (kt+1)%2
                                        // (iter 0: Q frags already extracted)
            issue_tile(kt + 1, (uint32_t)((kt + 1) & 1) * STAGE);
            CP_WAIT(1);                 // tile kt resident (kt+1 may be pending)
        } else {
            CP_WAIT(0);                 // last tile: everything resident
        }
        __syncthreads();                // cp.async writes visible to all warps

        const uint32_t stg = sb + (uint32_t)(kt & 1) * STAGE;

        // ---- S = Q.(Khi + Klo)  (2-pass fp16) ----
        float s[8][4];
        #pragma unroll
        for (int n = 0; n < 8; n++)
            #pragma unroll
            for (int j = 0; j < 4; j++) s[n][j] = 0.f;

        #pragma unroll
        for (int ks = 0; ks < 4; ks++) {
            #pragma unroll
            for (int kg = 0; kg < 4; kg++) {
                uint32_t addr = stg + swz((uint32_t)((kg * 16 + lr) * 128)
                                          + (uint32_t)((ks * 16 + lc) * 2));
                uint32_t bhf[4], blf[4];
                ldsm4(bhf, addr + P_KHI);
                mma_f16(s[2*kg],   qh[ks], bhf[0], bhf[2]);
                mma_f16(s[2*kg+1], qh[ks], bhf[1], bhf[3]);
                ldsm4(blf, addr + P_KLO);
                mma_f16(s[2*kg],   qh[ks], blf[0], blf[2]);
                mma_f16(s[2*kg+1], qh[ks], blf[1], blf[3]);
            }
        }

        // ---- causal mask (diagonal tile only) ----
        if (kt == qt) {
            #pragma unroll
            for (int n = 0; n < 8; n++) {
                int kb = kt * BN + n * 8 + quad * 2;
                if (kb     > qg0)     s[n][0] = -1e30f;
                if (kb + 1 > qg0)     s[n][1] = -1e30f;
                if (kb     > qg0 + 8) s[n][2] = -1e30f;
                if (kb + 1 > qg0 + 8) s[n][3] = -1e30f;
            }
        }

        // ---- online softmax (log2 domain) ----
        float mx0 = s[0][0], mx1 = s[0][2];
        #pragma unroll
        for (int n = 0; n < 8; n++) {
            mx0 = fmaxf(mx0, fmaxf(s[n][0], s[n][1]));
            mx1 = fmaxf(mx1, fmaxf(s[n][2], s[n][3]));
        }
        mx0 = fmaxf(mx0, __shfl_xor_sync(0xffffffffu, mx0, 1));
        mx0 = fmaxf(mx0, __shfl_xor_sync(0xffffffffu, mx0, 2));
        mx1 = fmaxf(mx1, __shfl_xor_sync(0xffffffffu, mx1, 1));
        mx1 = fmaxf(mx1, __shfl_xor_sync(0xffffffffu, mx1, 2));

        float mn0 = fmaxf(m0, mx0), mn1 = fmaxf(m1, mx1);
        float a0 = ex2(m0 - mn0), a1 = ex2(m1 - mn1);
        m0 = mn0; m1 = mn1;

        float rs0 = 0.f, rs1 = 0.f;
        #pragma unroll
        for (int n = 0; n < 8; n++) {
            s[n][0] = ex2(s[n][0] - m0); rs0 += s[n][0];
            s[n][1] = ex2(s[n][1] - m0); rs0 += s[n][1];
            s[n][2] = ex2(s[n][2] - m1); rs1 += s[n][2];
            s[n][3] = ex2(s[n][3] - m1); rs1 += s[n][3];
        }
        rs0 += __shfl_xor_sync(0xffffffffu, rs0, 1);
        rs0 += __shfl_xor_sync(0xffffffffu, rs0, 2);
        rs1 += __shfl_xor_sync(0xffffffffu, rs1, 1);
        rs1 += __shfl_xor_sync(0xffffffffu, rs1, 2);
        l0 = l0 * a0 + rs0;
        l1 = l1 * a1 + rs1;

        #pragma unroll
        for (int n = 0; n < 8; n++) {
            o[n][0] *= a0; o[n][1] *= a0;
            o[n][2] *= a1; o[n][3] *= a1;
        }

        // ---- P -> fp16 A-fragments (single precision pass) ----
        uint32_t pa[4][4];
        #pragma unroll
        for (int j = 0; j < 4; j++) {
            pa[j][0] = packh(s[2*j][0],   s[2*j][1]);
            pa[j][1] = packh(s[2*j][2],   s[2*j][3]);
            pa[j][2] = packh(s[2*j+1][0], s[2*j+1][1]);
            pa[j][3] = packh(s[2*j+1][2], s[2*j+1][3]);
        }

        // ---- O += P.(Vhi + Vlo)  (2-pass fp16) ----
        #pragma unroll
        for (int ks = 0; ks < 4; ks++) {
            #pragma unroll
            for (int dg = 0; dg < 4; dg++) {
                uint32_t addr = stg + swz((uint32_t)((ks * 16 + lr) * 128)
                                          + (uint32_t)((dg * 16 + lc) * 2));
                uint32_t vhf[4], vlf[4];
                ldsm4t(vhf, addr + P_VHI);
                mma_f16(o[2*dg],   pa[ks], vhf[0], vhf[1]);
                mma_f16(o[2*dg+1], pa[ks], vhf[2], vhf[3]);
                ldsm4t(vlf, addr + P_VLO);
                mma_f16(o[2*dg],   pa[ks], vlf[0], vlf[1]);
                mma_f16(o[2*dg+1], pa[ks], vlf[2], vlf[3]);
            }
        }
    }

    // ---- epilogue ----
    float inv0 = 1.0f / l0, inv1 = 1.0f / l1;
    float* Orow0 = Og + (rowbase + qg0) * DH;
    float* Orow1 = Orow0 + 8 * DH;
    #pragma unroll
    for (int n = 0; n < 8; n++) {
        int d = n * 8 + quad * 2;
        *(float2*)(Orow0 + d) = make_float2(o[n][0] * inv0, o[n][1] * inv0);
        *(float2*)(Orow1 + d) = make_float2(o[n][2] * inv1, o[n][3] * inv1);
    }
}

extern "C" void kernel_launch(void* const* d_in, const int* in_sizes, int n_in,
                              void* d_out, int out_size)
{
    const float* Q = (const float*)d_in[0];
    const float* K = (const float*)d_in[1];
    const float* V = (const float*)d_in[2];
    float* O = (float*)d_out;

    dim3 pgrid(NELEM / 4 / 256, 2);     // (4096, 2): K and V
    prep_kernel<<<pgrid, 256>>>(K, V);

    cudaFuncSetAttribute(fattn_mma_kernel,
                         cudaFuncAttributeMaxDynamicSharedMemorySize, SMEM_BYTES);
    dim3 grid(SEQ / BM, BHN);           // (32, 32)
    fattn_mma_kernel<<<grid, NTHR, SMEM_BYTES>>>(O, Q);
}

// round 10
// speedup vs baseline: 1.7672x; 1.1853x over previous
#include <cuda_runtime.h>
#include <cuda_fp16.h>
#include <cstdint>

// B=2,H=16,S=2048,D=64 causal attention, fp32 in/out.
#define BHN   32
#define SEQ   2048
#define DH    64
#define BM    64                        // q rows per CTA (4 warps x 16)
#define BN    64
#define NTHR  128
#define NELEM (BHN * SEQ * DH)          // 4,194,304

#define QSCALE 0.18033688f              // 0.125 * log2(e)

// ---- pre-converted fp16 operands: K hi+residual, V hi only ----
__device__ __align__(16) uint8_t gKhi[NELEM * 2];
__device__ __align__(16) uint8_t gKlo[NELEM * 2];
__device__ __align__(16) uint8_t gVhi[NELEM * 2];

// ---- smem: 2 stages x 24KB (KHI|KLO|VHI, 8KB each, XOR-swizzled) ----
#define STAGE   24576
#define P_KHI   0
#define P_KLO   8192
#define P_VHI   16384
#define SMEM_BYTES (2 * STAGE)          // 49152 -> 3 CTAs/SM

__device__ __forceinline__ uint32_t smem_u32(const void* p) {
    uint32_t a;
    asm("{ .reg .u64 t; cvta.to.shared.u64 t, %1; cvt.u32.u64 %0, t; }" : "=r"(a) : "l"(p));
    return a;
}
__device__ __forceinline__ uint32_t swz(uint32_t b) { return b ^ ((b >> 3) & 0x70u); }
__device__ __forceinline__ float ex2(float x) {
    float r; asm("ex2.approx.f32 %0, %1;" : "=f"(r) : "f"(x)); return r;
}
__device__ __forceinline__ void cpa16(uint32_t dst, const void* src) {
    asm volatile("cp.async.cg.shared.global [%0], [%1], 16;" :: "r"(dst), "l"(src));
}
#define CP_COMMIT() asm volatile("cp.async.commit_group;" ::: "memory")
#define CP_WAIT(n)  asm volatile("cp.async.wait_group %0;" :: "n"(n) : "memory")

__device__ __forceinline__ void ldsm4(uint32_t r[4], uint32_t addr) {
    asm volatile("ldmatrix.sync.aligned.m8n8.x4.shared.b16 {%0,%1,%2,%3}, [%4];"
        : "=r"(r[0]), "=r"(r[1]), "=r"(r[2]), "=r"(r[3]) : "r"(addr));
}
__device__ __forceinline__ void ldsm4t(uint32_t r[4], uint32_t addr) {
    asm volatile("ldmatrix.sync.aligned.m8n8.x4.trans.shared.b16 {%0,%1,%2,%3}, [%4];"
        : "=r"(r[0]), "=r"(r[1]), "=r"(r[2]), "=r"(r[3]) : "r"(addr));
}
// not volatile: lets ptxas schedule HMMA around FMA/MUFU chains
__device__ __forceinline__ void mma_f16(float c[4], const uint32_t a[4],
                                        uint32_t b0, uint32_t b1) {
    asm("mma.sync.aligned.m16n8k16.row.col.f32.f16.f16.f32 "
        "{%0,%1,%2,%3}, {%4,%5,%6,%7}, {%8,%9}, {%0,%1,%2,%3};"
        : "+f"(c[0]), "+f"(c[1]), "+f"(c[2]), "+f"(c[3])
        : "r"(a[0]), "r"(a[1]), "r"(a[2]), "r"(a[3]), "r"(b0), "r"(b1));
}
__device__ __forceinline__ uint32_t packh(float lo, float hi) {
    uint32_t r;
    asm("cvt.rn.f16x2.f32 %0, %1, %2;" : "=r"(r) : "f"(hi), "f"(lo));
    return r;
}
__device__ __forceinline__ void split2h(float x, float y, uint32_t& h, uint32_t& l) {
    h = packh(x, y);
    __half2 hh = *reinterpret_cast<__half2*>(&h);
    float hx = __half2float(__low2half(hh));
    float hy = __half2float(__high2half(hh));
    l = packh(x - hx, y - hy);
}

// ================= pre-pass: K -> fp16 hi/lo, V -> fp16 hi =================
__global__ __launch_bounds__(256)
void prep_kernel(const float* __restrict__ Kg, const float* __restrict__ Vg)
{
    const int i = blockIdx.x * 256 + threadIdx.x;      // per float4
    const int t = blockIdx.y;                          // 0=K 1=V
    const float4* src = (t == 0) ? (const float4*)Kg : (const float4*)Vg;
    uint2* hi = (t == 0) ? (uint2*)gKhi : (uint2*)gVhi;

    float4 v = src[i];
    uint2 h, l;
    split2h(v.x, v.y, h.x, l.x);
    split2h(v.z, v.w, h.y, l.y);
    hi[i] = h;
    if (t == 0) ((uint2*)gKlo)[i] = l;
}

// ================= main attention kernel =================
__global__ __launch_bounds__(NTHR, 3)
void fattn_mma_kernel(float* __restrict__ Og, const float* __restrict__ Qg)
{
    extern __shared__ __align__(1024) uint8_t smem[];
    const uint32_t sb = smem_u32(smem);

    const int tid  = threadIdx.x;
    const int w    = tid >> 5;           // 0..3
    const int lane = tid & 31;
    const int lr   = lane & 15;
    const int lc   = (lane >> 4) << 3;
    const int quad = lane & 3;

    const int qt = (gridDim.x - 1) - blockIdx.x;   // heavy tiles first
    const int bh = blockIdx.y;
    const size_t rowbase = (size_t)bh * SEQ;       // 128B-row index base

    const int n_kv = qt + 1;                       // kv tiles 0..qt (BM == BN)

    // tile issuer: one 24KB stage (KHI|KLO|VHI); 12 cp.async per thread
    auto issue_tile = [&](int kt, uint32_t stg) {
        const size_t tb = (rowbase + (size_t)kt * BN) * 128;
        const uint8_t* kh = gKhi + tb;
        const uint8_t* kl = gKlo + tb;
        const uint8_t* vh = gVhi + tb;
        #pragma unroll
        for (int j = 0; j < 4; j++) {
            uint32_t idx = (uint32_t)(tid + j * NTHR);
            uint32_t off = idx << 4;                 // 0..8176
            uint32_t so  = sb + stg + swz(off);
            cpa16(so + P_KHI, kh + off);
            cpa16(so + P_KLO, kl + off);
            cpa16(so + P_VHI, vh + off);
        }
        CP_COMMIT();
    };

    issue_tile(0, 0);                   // stage 0 in flight

    // ---- Q: load fp32, scale, fp16 pack, stage in stage-1 region (8KB) ----
    {
        const float* Qb = Qg + (rowbase + (size_t)qt * BM) * DH;
        #pragma unroll
        for (int it = 0; it < 8; it++) {
            int i  = tid + it * NTHR;   // 0..1023 float4
            int r  = i >> 4;
            int c4 = (i & 15) << 2;
            float4 v = *(const float4*)(Qb + r * DH + c4);
            uint2 h;
            h.x = packh(v.x * QSCALE, v.y * QSCALE);
            h.y = packh(v.z * QSCALE, v.w * QSCALE);
            *(uint2*)(smem + STAGE + swz((uint32_t)(r * 128 + c4 * 2))) = h;
        }
    }
    __syncthreads();

    uint32_t qh[4][4];
    {
        uint32_t rowb = (uint32_t)((w * 16 + lr) * 128);
        #pragma unroll
        for (int ks = 0; ks < 4; ks++)
            ldsm4(qh[ks], sb + STAGE + swz(rowb + (uint32_t)((ks * 16 + lc) * 2)));
    }

    float o[8][4];
    #pragma unroll
    for (int n = 0; n < 8; n++)
        #pragma unroll
        for (int j = 0; j < 4; j++) o[n][j] = 0.f;
    float m0 = -1e30f, m1 = -1e30f, l0 = 0.f, l1 = 0.f;

    const int qg0 = qt * BM + w * 16 + (lane >> 2);

    for (int kt = 0; kt < n_kv; kt++) {
        // guard the stage we are about to overwrite, then issue kt+1, then wait kt
        if (kt + 1 < n_kv) {
            __syncthreads();            // all warps done with stage (kt+1)%2
                                        // (iter 0: Q frags already extracted)
            issue_tile(kt + 1, (uint32_t)((kt + 1) & 1) * STAGE);
            CP_WAIT(1);                 // tile kt resident (kt+1 may be pending)
        } else {
            CP_WAIT(0);                 // last tile: everything resident
        }
        __syncthreads();                // cp.async writes visible to all warps

        const uint32_t stg = sb + (uint32_t)(kt & 1) * STAGE;

        // ---- S = Q.(Khi + Klo)  (2-pass fp16) ----
        float s[8][4];
        #pragma unroll
        for (int n = 0; n < 8; n++)
            #pragma unroll
            for (int j = 0; j < 4; j++) s[n][j] = 0.f;

        #pragma unroll
        for (int ks = 0; ks < 4; ks++) {
            #pragma unroll
            for (int kg = 0; kg < 4; kg++) {
                uint32_t addr = stg + swz((uint32_t)((kg * 16 + lr) * 128)
                                          + (uint32_t)((ks * 16 + lc) * 2));
                uint32_t bhf[4], blf[4];
                ldsm4(bhf, addr + P_KHI);
                mma_f16(s[2*kg],   qh[ks], bhf[0], bhf[2]);
                mma_f16(s[2*kg+1], qh[ks], bhf[1], bhf[3]);
                ldsm4(blf, addr + P_KLO);
                mma_f16(s[2*kg],   qh[ks], blf[0], blf[2]);
                mma_f16(s[2*kg+1], qh[ks], blf[1], blf[3]);
            }
        }

        // ---- causal mask (diagonal tile only) ----
        if (kt == qt) {
            #pragma unroll
            for (int n = 0; n < 8; n++) {
                int kb = kt * BN + n * 8 + quad * 2;
                if (kb     > qg0)     s[n][0] = -1e30f;
                if (kb + 1 > qg0)     s[n][1] = -1e30f;
                if (kb     > qg0 + 8) s[n][2] = -1e30f;
                if (kb + 1 > qg0 + 8) s[n][3] = -1e30f;
            }
        }

        // ---- online softmax (log2 domain) ----
        float mx0 = s[0][0], mx1 = s[0][2];
        #pragma unroll
        for (int n = 0; n < 8; n++) {
            mx0 = fmaxf(mx0, fmaxf(s[n][0], s[n][1]));
            mx1 = fmaxf(mx1, fmaxf(s[n][2], s[n][3]));
        }
        mx0 = fmaxf(mx0, __shfl_xor_sync(0xffffffffu, mx0, 1));
        mx0 = fmaxf(mx0, __shfl_xor_sync(0xffffffffu, mx0, 2));
        mx1 = fmaxf(mx1, __shfl_xor_sync(0xffffffffu, mx1, 1));
        mx1 = fmaxf(mx1, __shfl_xor_sync(0xffffffffu, mx1, 2));

        float mn0 = fmaxf(m0, mx0), mn1 = fmaxf(m1, mx1);
        float a0 = ex2(m0 - mn0), a1 = ex2(m1 - mn1);
        m0 = mn0; m1 = mn1;

        float rs0 = 0.f, rs1 = 0.f;
        #pragma unroll
        for (int n = 0; n < 8; n++) {
            s[n][0] = ex2(s[n][0] - m0); rs0 += s[n][0];
            s[n][1] = ex2(s[n][1] - m0); rs0 += s[n][1];
            s[n][2] = ex2(s[n][2] - m1); rs1 += s[n][2];
            s[n][3] = ex2(s[n][3] - m1); rs1 += s[n][3];
        }
        rs0 += __shfl_xor_sync(0xffffffffu, rs0, 1);
        rs0 += __shfl_xor_sync(0xffffffffu, rs0, 2);
        rs1 += __shfl_xor_sync(0xffffffffu, rs1, 1);
        rs1 += __shfl_xor_sync(0xffffffffu, rs1, 2);
        l0 = l0 * a0 + rs0;
        l1 = l1 * a1 + rs1;

        #pragma unroll
        for (int n = 0; n < 8; n++) {
            o[n][0] *= a0; o[n][1] *= a0;
            o[n][2] *= a1; o[n][3] *= a1;
        }

        // ---- P -> fp16 A-fragments ----
        uint32_t pa[4][4];
        #pragma unroll
        for (int j = 0; j < 4; j++) {
            pa[j][0] = packh(s[2*j][0],   s[2*j][1]);
            pa[j][1] = packh(s[2*j][2],   s[2*j][3]);
            pa[j][2] = packh(s[2*j+1][0], s[2*j+1][1]);
            pa[j][3] = packh(s[2*j+1][2], s[2*j+1][3]);
        }

        // ---- O += P.Vhi  (single-pass fp16) ----
        #pragma unroll
        for (int ks = 0; ks < 4; ks++) {
            #pragma unroll
            for (int dg = 0; dg < 4; dg++) {
                uint32_t addr = stg + swz((uint32_t)((ks * 16 + lr) * 128)
                                          + (uint32_t)((dg * 16 + lc) * 2));
                uint32_t vhf[4];
                ldsm4t(vhf, addr + P_VHI);
                mma_f16(o[2*dg],   pa[ks], vhf[0], vhf[1]);
                mma_f16(o[2*dg+1], pa[ks], vhf[2], vhf[3]);
            }
        }
    }

    // ---- epilogue ----
    float inv0 = 1.0f / l0, inv1 = 1.0f / l1;
    float* Orow0 = Og + (rowbase + qg0) * DH;
    float* Orow1 = Orow0 + 8 * DH;
    #pragma unroll
    for (int n = 0; n < 8; n++) {
        int d = n * 8 + quad * 2;
        *(float2*)(Orow0 + d) = make_float2(o[n][0] * inv0, o[n][1] * inv0);
        *(float2*)(Orow1 + d) = make_float2(o[n][2] * inv1, o[n][3] * inv1);
    }
}

extern "C" void kernel_launch(void* const* d_in, const int* in_sizes, int n_in,
                              void* d_out, int out_size)
{
    const float* Q = (const float*)d_in[0];
    const float* K = (const float*)d_in[1];
    const float* V = (const float*)d_in[2];
    float* O = (float*)d_out;

    dim3 pgrid(NELEM / 4 / 256, 2);     // (4096, 2): K and V
    prep_kernel<<<pgrid, 256>>>(K, V);

    cudaFuncSetAttribute(fattn_mma_kernel,
                         cudaFuncAttributeMaxDynamicSharedMemorySize, SMEM_BYTES);
    dim3 grid(SEQ / BM, BHN);           // (32, 32)
    fattn_mma_kernel<<<grid, NTHR, SMEM_BYTES>>>(O, Q);
}

// round 11
// speedup vs baseline: 2.2528x; 1.2748x over previous
#include <cuda_runtime.h>
#include <cuda_fp16.h>
#include <cstdint>

// B=2,H=16,S=2048,D=64 causal attention, fp32 in/out.
#define BHN   32
#define SEQ   2048
#define DH    64
#define BM    64                        // q rows per CTA (4 warps x 16)
#define BN    64
#define NTHR  128
#define NELEM (BHN * SEQ * DH)          // 4,194,304

#define QSCALE 0.18033688f              // 0.125 * log2(e)

// ---- pre-converted fp16 operands (single precision, round-to-nearest) ----
__device__ __align__(16) uint8_t gKhi[NELEM * 2];
__device__ __align__(16) uint8_t gVhi[NELEM * 2];

// ---- smem: 3 stages x 16KB (KHI|VHI, 8KB each, XOR-swizzled) ----
#define STAGE   16384
#define P_KHI   0
#define P_VHI   8192
#define SMEM_BYTES (3 * STAGE)          // 49152 -> 3 CTAs/SM

__device__ __forceinline__ uint32_t smem_u32(const void* p) {
    uint32_t a;
    asm("{ .reg .u64 t; cvta.to.shared.u64 t, %1; cvt.u32.u64 %0, t; }" : "=r"(a) : "l"(p));
    return a;
}
__device__ __forceinline__ uint32_t swz(uint32_t b) { return b ^ ((b >> 3) & 0x70u); }
__device__ __forceinline__ float ex2(float x) {
    float r; asm("ex2.approx.f32 %0, %1;" : "=f"(r) : "f"(x)); return r;
}
__device__ __forceinline__ void cpa16(uint32_t dst, const void* src) {
    asm volatile("cp.async.cg.shared.global [%0], [%1], 16;" :: "r"(dst), "l"(src));
}
#define CP_COMMIT() asm volatile("cp.async.commit_group;" ::: "memory")
#define CP_WAIT(n)  asm volatile("cp.async.wait_group %0;" :: "n"(n) : "memory")

__device__ __forceinline__ void ldsm4(uint32_t r[4], uint32_t addr) {
    asm volatile("ldmatrix.sync.aligned.m8n8.x4.shared.b16 {%0,%1,%2,%3}, [%4];"
        : "=r"(r[0]), "=r"(r[1]), "=r"(r[2]), "=r"(r[3]) : "r"(addr));
}
__device__ __forceinline__ void ldsm4t(uint32_t r[4], uint32_t addr) {
    asm volatile("ldmatrix.sync.aligned.m8n8.x4.trans.shared.b16 {%0,%1,%2,%3}, [%4];"
        : "=r"(r[0]), "=r"(r[1]), "=r"(r[2]), "=r"(r[3]) : "r"(addr));
}
// not volatile: lets ptxas schedule HMMA around FMA/MUFU chains
__device__ __forceinline__ void mma_f16(float c[4], const uint32_t a[4],
                                        uint32_t b0, uint32_t b1) {
    asm("mma.sync.aligned.m16n8k16.row.col.f32.f16.f16.f32 "
        "{%0,%1,%2,%3}, {%4,%5,%6,%7}, {%8,%9}, {%0,%1,%2,%3};"
        : "+f"(c[0]), "+f"(c[1]), "+f"(c[2]), "+f"(c[3])
        : "r"(a[0]), "r"(a[1]), "r"(a[2]), "r"(a[3]), "r"(b0), "r"(b1));
}
__device__ __forceinline__ uint32_t packh(float lo, float hi) {
    uint32_t r;
    asm("cvt.rn.f16x2.f32 %0, %1, %2;" : "=r"(r) : "f"(hi), "f"(lo));
    return r;
}

// ================= pre-pass: K,V fp32 -> fp16 =================
__global__ __launch_bounds__(256)
void prep_kernel(const float* __restrict__ Kg, const float* __restrict__ Vg)
{
    const int i = blockIdx.x * 256 + threadIdx.x;      // per float4
    const int t = blockIdx.y;                          // 0=K 1=V
    const float4* src = (t == 0) ? (const float4*)Kg : (const float4*)Vg;
    uint2* hi = (t == 0) ? (uint2*)gKhi : (uint2*)gVhi;

    float4 v = src[i];
    uint2 h;
    h.x = packh(v.x, v.y);
    h.y = packh(v.z, v.w);
    hi[i] = h;
}

// ================= main attention kernel =================
__global__ __launch_bounds__(NTHR, 3)
void fattn_mma_kernel(float* __restrict__ Og, const float* __restrict__ Qg)
{
    extern __shared__ __align__(1024) uint8_t smem[];
    const uint32_t sb = smem_u32(smem);

    const int tid  = threadIdx.x;
    const int w    = tid >> 5;           // 0..3
    const int lane = tid & 31;
    const int lr   = lane & 15;
    const int lc   = (lane >> 4) << 3;
    const int quad = lane & 3;

    const int qt = (gridDim.x - 1) - blockIdx.x;   // heavy tiles first
    const int bh = blockIdx.y;
    const size_t rowbase = (size_t)bh * SEQ;       // 128B-row index base

    const int n_kv = qt + 1;                       // kv tiles 0..qt (BM == BN)

    // tile issuer: one 16KB stage (KHI|VHI); 8 cp.async per thread
    auto issue_tile = [&](int kt, uint32_t stg) {
        const size_t tb = (rowbase + (size_t)kt * BN) * 128;
        const uint8_t* kh = gKhi + tb;
        const uint8_t* vh = gVhi + tb;
        #pragma unroll
        for (int j = 0; j < 4; j++) {
            uint32_t idx = (uint32_t)(tid + j * NTHR);
            uint32_t off = idx << 4;                 // 0..8176
            uint32_t so  = sb + stg + swz(off);
            cpa16(so + P_KHI, kh + off);
            cpa16(so + P_VHI, vh + off);
        }
        CP_COMMIT();
    };

    issue_tile(0, 0);                   // tile 0 -> stage 0

    // ---- Q: load fp32, scale, fp16 pack, stage in stage-2 region (8KB) ----
    {
        const float* Qb = Qg + (rowbase + (size_t)qt * BM) * DH;
        #pragma unroll
        for (int it = 0; it < 8; it++) {
            int i  = tid + it * NTHR;   // 0..1023 float4
            int r  = i >> 4;
            int c4 = (i & 15) << 2;
            float4 v = *(const float4*)(Qb + r * DH + c4);
            uint2 h;
            h.x = packh(v.x * QSCALE, v.y * QSCALE);
            h.y = packh(v.z * QSCALE, v.w * QSCALE);
            *(uint2*)(smem + 2 * STAGE + swz((uint32_t)(r * 128 + c4 * 2))) = h;
        }
    }
    __syncthreads();

    uint32_t qh[4][4];
    {
        uint32_t rowb = (uint32_t)((w * 16 + lr) * 128);
        #pragma unroll
        for (int ks = 0; ks < 4; ks++)
            ldsm4(qh[ks], sb + 2 * STAGE + swz(rowb + (uint32_t)((ks * 16 + lc) * 2)));
    }
    __syncthreads();                    // stage-2 region free (Q extracted)
    if (qt >= 1) issue_tile(1, STAGE);  // tile 1 -> stage 1

    float o[8][4];
    #pragma unroll
    for (int n = 0; n < 8; n++)
        #pragma unroll
        for (int j = 0; j < 4; j++) o[n][j] = 0.f;
    float m0 = -1e30f, m1 = -1e30f, l0 = 0.f, l1 = 0.f;

    const int qg0 = qt * BM + w * 16 + (lane >> 2);

    for (int kt = 0; kt < n_kv; kt++) {
        // guard stage (kt+2)%3 (its previous tile kt-1 was consumed last iter),
        // issue tile kt+2 into it, then wait for tile kt.
        __syncthreads();
        if (kt + 2 <= qt) {
            issue_tile(kt + 2, (uint32_t)((kt + 2) % 3) * STAGE);
            CP_WAIT(2);                 // tile kt resident; kt+1, kt+2 pending
        } else if (kt + 1 <= qt) {
            CP_WAIT(1);                 // tile kt resident; kt+1 pending
        } else {
            CP_WAIT(0);                 // last tile
        }
        __syncthreads();                // cp.async writes visible to all warps

        const uint32_t stg = sb + (uint32_t)(kt % 3) * STAGE;

        // ---- S = Q.Khi  (single-pass fp16) ----
        float s[8][4];
        #pragma unroll
        for (int n = 0; n < 8; n++)
            #pragma unroll
            for (int j = 0; j < 4; j++) s[n][j] = 0.f;

        #pragma unroll
        for (int ks = 0; ks < 4; ks++) {
            #pragma unroll
            for (int kg = 0; kg < 4; kg++) {
                uint32_t addr = stg + swz((uint32_t)((kg * 16 + lr) * 128)
                                          + (uint32_t)((ks * 16 + lc) * 2));
                uint32_t bhf[4];
                ldsm4(bhf, addr + P_KHI);
                mma_f16(s[2*kg],   qh[ks], bhf[0], bhf[2]);
                mma_f16(s[2*kg+1], qh[ks], bhf[1], bhf[3]);
            }
        }

        // ---- causal mask (diagonal tile only) ----
        if (kt == qt) {
            #pragma unroll
            for (int n = 0; n < 8; n++) {
                int kb = kt * BN + n * 8 + quad * 2;
                if (kb     > qg0)     s[n][0] = -1e30f;
                if (kb + 1 > qg0)     s[n][1] = -1e30f;
                if (kb     > qg0 + 8) s[n][2] = -1e30f;
                if (kb + 1 > qg0 + 8) s[n][3] = -1e30f;
            }
        }

        // ---- online softmax (log2 domain) ----
        float mx0 = s[0][0], mx1 = s[0][2];
        #pragma unroll
        for (int n = 0; n < 8; n++) {
            mx0 = fmaxf(mx0, fmaxf(s[n][0], s[n][1]));
            mx1 = fmaxf(mx1, fmaxf(s[n][2], s[n][3]));
        }
        mx0 = fmaxf(mx0, __shfl_xor_sync(0xffffffffu, mx0, 1));
        mx0 = fmaxf(mx0, __shfl_xor_sync(0xffffffffu, mx0, 2));
        mx1 = fmaxf(mx1, __shfl_xor_sync(0xffffffffu, mx1, 1));
        mx1 = fmaxf(mx1, __shfl_xor_sync(0xffffffffu, mx1, 2));

        float mn0 = fmaxf(m0, mx0), mn1 = fmaxf(m1, mx1);
        float a0 = ex2(m0 - mn0), a1 = ex2(m1 - mn1);
        m0 = mn0; m1 = mn1;

        float rs0 = 0.f, rs1 = 0.f;
        #pragma unroll
        for (int n = 0; n < 8; n++) {
            s[n][0] = ex2(s[n][0] - m0); rs0 += s[n][0];
            s[n][1] = ex2(s[n][1] - m0); rs0 += s[n][1];
            s[n][2] = ex2(s[n][2] - m1); rs1 += s[n][2];
            s[n][3] = ex2(s[n][3] - m1); rs1 += s[n][3];
        }
        rs0 += __shfl_xor_sync(0xffffffffu, rs0, 1);
        rs0 += __shfl_xor_sync(0xffffffffu, rs0, 2);
        rs1 += __shfl_xor_sync(0xffffffffu, rs1, 1);
        rs1 += __shfl_xor_sync(0xffffffffu, rs1, 2);
        l0 = l0 * a0 + rs0;
        l1 = l1 * a1 + rs1;

        #pragma unroll
        for (int n = 0; n < 8; n++) {
            o[n][0] *= a0; o[n][1] *= a0;
            o[n][2] *= a1; o[n][3] *= a1;
        }

        // ---- P -> fp16 A-fragments ----
        uint32_t pa[4][4];
        #pragma unroll
        for (int j = 0; j < 4; j++) {
            pa[j][0] = packh(s[2*j][0],   s[2*j][1]);
            pa[j][1] = packh(s[2*j][2],   s[2*j][3]);
            pa[j][2] = packh(s[2*j+1][0], s[2*j+1][1]);
            pa[j][3] = packh(s[2*j+1][2], s[2*j+1][3]);
        }

        // ---- O += P.Vhi  (single-pass fp16) ----
        #pragma unroll
        for (int ks = 0; ks < 4; ks++) {
            #pragma unroll
            for (int dg = 0; dg < 4; dg++) {
                uint32_t addr = stg + swz((uint32_t)((ks * 16 + lr) * 128)
                                          + (uint32_t)((dg * 16 + lc) * 2));
                uint32_t vhf[4];
                ldsm4t(vhf, addr + P_VHI);
                mma_f16(o[2*dg],   pa[ks], vhf[0], vhf[1]);
                mma_f16(o[2*dg+1], pa[ks], vhf[2], vhf[3]);
            }
        }
    }

    // ---- epilogue ----
    float inv0 = 1.0f / l0, inv1 = 1.0f / l1;
    float* Orow0 = Og + (rowbase + qg0) * DH;
    float* Orow1 = Orow0 + 8 * DH;
    #pragma unroll
    for (int n = 0; n < 8; n++) {
        int d = n * 8 + quad * 2;
        *(float2*)(Orow0 + d) = make_float2(o[n][0] * inv0, o[n][1] * inv0);
        *(float2*)(Orow1 + d) = make_float2(o[n][2] * inv1, o[n][3] * inv1);
    }
}

extern "C" void kernel_launch(void* const* d_in, const int* in_sizes, int n_in,
                              void* d_out, int out_size)
{
    const float* Q = (const float*)d_in[0];
    const float* K = (const float*)d_in[1];
    const float* V = (const float*)d_in[2];
    float* O = (float*)d_out;

    dim3 pgrid(NELEM / 4 / 256, 2);     // (4096, 2): K and V
    prep_kernel<<<pgrid, 256>>>(K, V);

    cudaFuncSetAttribute(fattn_mma_kernel,
                         cudaFuncAttributeMaxDynamicSharedMemorySize, SMEM_BYTES);
    dim3 grid(SEQ / BM, BHN);           // (32, 32)
    fattn_mma_kernel<<<grid, NTHR, SMEM_BYTES>>>(O, Q);
}

// round 12
// speedup vs baseline: 2.4245x; 1.0762x over previous
#include <cuda_runtime.h>
#include <cuda_fp16.h>
#include <cstdint>

// B=2,H=16,S=2048,D=64 causal attention, fp32 in/out.
#define BHN   32
#define SEQ   2048
#define DH    64
#define BM    64                        // q rows per CTA (4 warps x 16)
#define BN    64
#define NTHR  128
#define NELEM (BHN * SEQ * DH)          // 4,194,304

#define QSCALE 0.18033688f              // 0.125 * log2(e)
#define ONESH2 0x3C003C00u              // fp16x2 {1.0, 1.0}

// ---- pre-converted fp16 operands ----
__device__ __align__(16) uint8_t gKhi[NELEM * 2];
__device__ __align__(16) uint8_t gVhi[NELEM * 2];

// ---- smem: 3 stages x 16KB (KHI|VHI, 8KB each, XOR-swizzled) ----
#define STAGE   16384
#define P_KHI   0
#define P_VHI   8192
#define SMEM_BYTES (3 * STAGE)          // 49152 -> 3 CTAs/SM

__device__ __forceinline__ uint32_t smem_u32(const void* p) {
    uint32_t a;
    asm("{ .reg .u64 t; cvta.to.shared.u64 t, %1; cvt.u32.u64 %0, t; }" : "=r"(a) : "l"(p));
    return a;
}
__device__ __forceinline__ uint32_t swz(uint32_t b) { return b ^ ((b >> 3) & 0x70u); }
__device__ __forceinline__ float ex2(float x) {
    float r; asm("ex2.approx.f32 %0, %1;" : "=f"(r) : "f"(x)); return r;
}
__device__ __forceinline__ uint32_t ex2h2(uint32_t x) {
    uint32_t r; asm("ex2.approx.f16x2 %0, %1;" : "=r"(r) : "r"(x)); return r;
}
__device__ __forceinline__ void cpa16(uint32_t dst, const void* src) {
    asm volatile("cp.async.cg.shared.global [%0], [%1], 16;" :: "r"(dst), "l"(src));
}
#define CP_COMMIT() asm volatile("cp.async.commit_group;" ::: "memory")
#define CP_WAIT(n)  asm volatile("cp.async.wait_group %0;" :: "n"(n) : "memory")

__device__ __forceinline__ void ldsm4(uint32_t r[4], uint32_t addr) {
    asm volatile("ldmatrix.sync.aligned.m8n8.x4.shared.b16 {%0,%1,%2,%3}, [%4];"
        : "=r"(r[0]), "=r"(r[1]), "=r"(r[2]), "=r"(r[3]) : "r"(addr));
}
__device__ __forceinline__ void ldsm4t(uint32_t r[4], uint32_t addr) {
    asm volatile("ldmatrix.sync.aligned.m8n8.x4.trans.shared.b16 {%0,%1,%2,%3}, [%4];"
        : "=r"(r[0]), "=r"(r[1]), "=r"(r[2]), "=r"(r[3]) : "r"(addr));
}
// not volatile: lets ptxas schedule HMMA around FMA/MUFU chains
__device__ __forceinline__ void mma_f16(float c[4], const uint32_t a[4],
                                        uint32_t b0, uint32_t b1) {
    asm("mma.sync.aligned.m16n8k16.row.col.f32.f16.f16.f32 "
        "{%0,%1,%2,%3}, {%4,%5,%6,%7}, {%8,%9}, {%0,%1,%2,%3};"
        : "+f"(c[0]), "+f"(c[1]), "+f"(c[2]), "+f"(c[3])
        : "r"(a[0]), "r"(a[1]), "r"(a[2]), "r"(a[3]), "r"(b0), "r"(b1));
}
__device__ __forceinline__ uint32_t packh(float lo, float hi) {
    uint32_t r;
    asm("cvt.rn.f16x2.f32 %0, %1, %2;" : "=r"(r) : "f"(hi), "f"(lo));
    return r;
}

// ================= pre-pass: K,V fp32 -> fp16 =================
__global__ __launch_bounds__(256)
void prep_kernel(const float* __restrict__ Kg, const float* __restrict__ Vg)
{
    const int i = blockIdx.x * 256 + threadIdx.x;      // per float4
    const int t = blockIdx.y;                          // 0=K 1=V
    const float4* src = (t == 0) ? (const float4*)Kg : (const float4*)Vg;
    uint2* hi = (t == 0) ? (uint2*)gKhi : (uint2*)gVhi;

    float4 v = src[i];
    uint2 h;
    h.x = packh(v.x, v.y);
    h.y = packh(v.z, v.w);
    hi[i] = h;
}

// ================= main attention kernel =================
__global__ __launch_bounds__(NTHR, 3)
void fattn_mma_kernel(float* __restrict__ Og, const float* __restrict__ Qg)
{
    extern __shared__ __align__(1024) uint8_t smem[];
    const uint32_t sb = smem_u32(smem);

    const int tid  = threadIdx.x;
    const int w    = tid >> 5;           // 0..3
    const int lane = tid & 31;
    const int lr   = lane & 15;
    const int lc   = (lane >> 4) << 3;
    const int quad = lane & 3;

    const int qt = (gridDim.x - 1) - blockIdx.x;   // heavy tiles first
    const int bh = blockIdx.y;
    const size_t rowbase = (size_t)bh * SEQ;       // 128B-row index base

    const int n_kv = qt + 1;                       // kv tiles 0..qt (BM == BN)

    // hoisted swizzled address components:
    // swz(row*128 + col) == row*128 + (col ^ ((lr&7)<<4))  for col in [0,128)
    const uint32_t xorp = (uint32_t)((lr & 7) << 4);
    uint32_t rowoff[4], coloff[4];
    #pragma unroll
    for (int g = 0; g < 4; g++) {
        rowoff[g] = (uint32_t)((g * 16 + lr) * 128);
        coloff[g] = ((uint32_t)(g * 32 + lc * 2)) ^ xorp;
    }

    // tile issuer: one 16KB stage (KHI|VHI); 8 cp.async per thread
    auto issue_tile = [&](int kt, uint32_t stg) {
        const size_t tb = (rowbase + (size_t)kt * BN) * 128;
        const uint8_t* kh = gKhi + tb;
        const uint8_t* vh = gVhi + tb;
        #pragma unroll
        for (int j = 0; j < 4; j++) {
            uint32_t idx = (uint32_t)(tid + j * NTHR);
            uint32_t off = idx << 4;                 // 0..8176
            uint32_t so  = sb + stg + swz(off);
            cpa16(so + P_KHI, kh + off);
            cpa16(so + P_VHI, vh + off);
        }
        CP_COMMIT();
    };

    issue_tile(0, 0);                   // tile 0 -> stage 0

    // ---- Q: load fp32, scale, fp16 pack, stage in stage-2 region (8KB) ----
    {
        const float* Qb = Qg + (rowbase + (size_t)qt * BM) * DH;
        #pragma unroll
        for (int it = 0; it < 8; it++) {
            int i  = tid + it * NTHR;   // 0..1023 float4
            int r  = i >> 4;
            int c4 = (i & 15) << 2;
            float4 v = *(const float4*)(Qb + r * DH + c4);
            uint2 h;
            h.x = packh(v.x * QSCALE, v.y * QSCALE);
            h.y = packh(v.z * QSCALE, v.w * QSCALE);
            *(uint2*)(smem + 2 * STAGE + swz((uint32_t)(r * 128 + c4 * 2))) = h;
        }
    }
    __syncthreads();

    uint32_t qh[4][4];
    #pragma unroll
    for (int ks = 0; ks < 4; ks++)
        ldsm4(qh[ks], sb + 2 * STAGE + rowoff[w] + coloff[ks]);
    __syncthreads();                    // stage-2 region free (Q extracted)
    if (qt >= 1) issue_tile(1, STAGE);  // tile 1 -> stage 1

    float o[8][4];
    #pragma unroll
    for (int n = 0; n < 8; n++)
        #pragma unroll
        for (int j = 0; j < 4; j++) o[n][j] = 0.f;
    float ol[4] = {0.f, 0.f, 0.f, 0.f};  // ones-column accum: row sums of P
    float m0 = -1e30f, m1 = -1e30f;

    const int qg0 = qt * BM + w * 16 + (lane >> 2);

    for (int kt = 0; kt < n_kv; kt++) {
        // guard stage (kt+2)%3, issue tile kt+2 into it, then wait for tile kt
        __syncthreads();
        if (kt + 2 <= qt) {
            issue_tile(kt + 2, (uint32_t)((kt + 2) % 3) * STAGE);
            CP_WAIT(2);                 // tile kt resident; kt+1, kt+2 pending
        } else if (kt + 1 <= qt) {
            CP_WAIT(1);                 // tile kt resident; kt+1 pending
        } else {
            CP_WAIT(0);                 // last tile
        }
        __syncthreads();                // cp.async writes visible to all warps

        const uint32_t stg = sb + (uint32_t)(kt % 3) * STAGE;

        // ---- S = Q.Khi  (single-pass fp16) ----
        float s[8][4];
        #pragma unroll
        for (int n = 0; n < 8; n++)
            #pragma unroll
            for (int j = 0; j < 4; j++) s[n][j] = 0.f;

        #pragma unroll
        for (int ks = 0; ks < 4; ks++) {
            #pragma unroll
            for (int kg = 0; kg < 4; kg++) {
                uint32_t bhf[4];
                ldsm4(bhf, stg + P_KHI + rowoff[kg] + coloff[ks]);
                mma_f16(s[2*kg],   qh[ks], bhf[0], bhf[2]);
                mma_f16(s[2*kg+1], qh[ks], bhf[1], bhf[3]);
            }
        }

        // ---- causal mask (diagonal tile only) ----
        if (kt == qt) {
            #pragma unroll
            for (int n = 0; n < 8; n++) {
                int kb = kt * BN + n * 8 + quad * 2;
                if (kb     > qg0)     s[n][0] = -30000.f;
                if (kb + 1 > qg0)     s[n][1] = -30000.f;
                if (kb     > qg0 + 8) s[n][2] = -30000.f;
                if (kb + 1 > qg0 + 8) s[n][3] = -30000.f;
            }
        }

        // ---- online softmax (log2 domain), l folded into PV via ones column ----
        float mx0 = s[0][0], mx1 = s[0][2];
        #pragma unroll
        for (int n = 0; n < 8; n++) {
            mx0 = fmaxf(mx0, fmaxf(s[n][0], s[n][1]));
            mx1 = fmaxf(mx1, fmaxf(s[n][2], s[n][3]));
        }
        mx0 = fmaxf(mx0, __shfl_xor_sync(0xffffffffu, mx0, 1));
        mx0 = fmaxf(mx0, __shfl_xor_sync(0xffffffffu, mx0, 2));
        mx1 = fmaxf(mx1, __shfl_xor_sync(0xffffffffu, mx1, 1));
        mx1 = fmaxf(mx1, __shfl_xor_sync(0xffffffffu, mx1, 2));

        if (__any_sync(0xffffffffu, (mx0 > m0) || (mx1 > m1))) {
            float mn0 = fmaxf(m0, mx0), mn1 = fmaxf(m1, mx1);
            float a0 = ex2(m0 - mn0), a1 = ex2(m1 - mn1);
            m0 = mn0; m1 = mn1;
            #pragma unroll
            for (int n = 0; n < 8; n++) {
                o[n][0] *= a0; o[n][1] *= a0;
                o[n][2] *= a1; o[n][3] *= a1;
            }
            ol[0] *= a0; ol[1] *= a0;
            ol[2] *= a1; ol[3] *= a1;
        }

        // ---- P = exp2(s - m) computed directly in fp16x2 A-fragments ----
        uint32_t pa[4][4];
        #pragma unroll
        for (int j = 0; j < 4; j++) {
            pa[j][0] = ex2h2(packh(s[2*j][0]   - m0, s[2*j][1]   - m0));
            pa[j][1] = ex2h2(packh(s[2*j][2]   - m1, s[2*j][3]   - m1));
            pa[j][2] = ex2h2(packh(s[2*j+1][0] - m0, s[2*j+1][1] - m0));
            pa[j][3] = ex2h2(packh(s[2*j+1][2] - m1, s[2*j+1][3] - m1));
        }

        // ---- O += P.Vhi ; ol += P.1 (ones column, constant B-frag) ----
        #pragma unroll
        for (int ks = 0; ks < 4; ks++) {
            #pragma unroll
            for (int dg = 0; dg < 4; dg++) {
                uint32_t vhf[4];
                ldsm4t(vhf, stg + P_VHI + rowoff[ks] + coloff[dg]);
                mma_f16(o[2*dg],   pa[ks], vhf[0], vhf[1]);
                mma_f16(o[2*dg+1], pa[ks], vhf[2], vhf[3]);
            }
            mma_f16(ol, pa[ks], ONESH2, ONESH2);
        }
    }

    // ---- epilogue: normalize by ones-column sums ----
    float inv0 = 1.0f / ol[0], inv1 = 1.0f / ol[2];
    float* Orow0 = Og + (rowbase + qg0) * DH;
    float* Orow1 = Orow0 + 8 * DH;
    #pragma unroll
    for (int n = 0; n < 8; n++) {
        int d = n * 8 + quad * 2;
        *(float2*)(Orow0 + d) = make_float2(o[n][0] * inv0, o[n][1] * inv0);
        *(float2*)(Orow1 + d) = make_float2(o[n][2] * inv1, o[n][3] * inv1);
    }
}

extern "C" void kernel_launch(void* const* d_in, const int* in_sizes, int n_in,
                              void* d_out, int out_size)
{
    const float* Q = (const float*)d_in[0];
    const float* K = (const float*)d_in[1];
    const float* V = (const float*)d_in[2];
    float* O = (float*)d_out;

    dim3 pgrid(NELEM / 4 / 256, 2);     // (4096, 2): K and V
    prep_kernel<<<pgrid, 256>>>(K, V);

    cudaFuncSetAttribute(fattn_mma_kernel,
                         cudaFuncAttributeMaxDynamicSharedMemorySize, SMEM_BYTES);
    dim3 grid(SEQ / BM, BHN);           // (32, 32)
    fattn_mma_kernel<<<grid, NTHR, SMEM_BYTES>>>(O, Q);
}

// round 13
// speedup vs baseline: 2.5326x; 1.0446x over previous
#include <cuda_runtime.h>
#include <cuda_fp16.h>
#include <cstdint>

// B=2,H=16,S=2048,D=64 causal attention, fp32 in/out.
#define BHN   32
#define SEQ   2048
#define DH    64
#define BM    64                        // q rows per CTA (4 warps x 16)
#define BN    64
#define NTHR  128
#define NELEM (BHN * SEQ * DH)          // 4,194,304

#define QSCALE 0.18033688f              // 0.125 * log2(e)
#define ONESH2 0x3C003C00u              // fp16x2 {1.0, 1.0}

// ---- pre-converted fp16 operands ----
__device__ __align__(16) uint8_t gKhi[NELEM * 2];
__device__ __align__(16) uint8_t gVhi[NELEM * 2];

// ---- smem: 4 stages x 16KB (KHI|VHI, 8KB each, XOR-swizzled) ----
#define STAGE   16384
#define P_KHI   0
#define P_VHI   8192
#define SMEM_BYTES (4 * STAGE)          // 65536 -> 3 CTAs/SM (192KB)

__device__ __forceinline__ uint32_t smem_u32(const void* p) {
    uint32_t a;
    asm("{ .reg .u64 t; cvta.to.shared.u64 t, %1; cvt.u32.u64 %0, t; }" : "=r"(a) : "l"(p));
    return a;
}
__device__ __forceinline__ uint32_t swz(uint32_t b) { return b ^ ((b >> 3) & 0x70u); }
__device__ __forceinline__ float ex2(float x) {
    float r; asm("ex2.approx.f32 %0, %1;" : "=f"(r) : "f"(x)); return r;
}
__device__ __forceinline__ uint32_t ex2h2(uint32_t x) {
    uint32_t r; asm("ex2.approx.f16x2 %0, %1;" : "=r"(r) : "r"(x)); return r;
}
__device__ __forceinline__ void cpa16(uint32_t dst, const void* src) {
    asm volatile("cp.async.cg.shared.global [%0], [%1], 16;" :: "r"(dst), "l"(src));
}
#define CP_COMMIT() asm volatile("cp.async.commit_group;" ::: "memory")
#define CP_WAIT(n)  asm volatile("cp.async.wait_group %0;" :: "n"(n) : "memory")

__device__ __forceinline__ void ldsm4(uint32_t r[4], uint32_t addr) {
    asm volatile("ldmatrix.sync.aligned.m8n8.x4.shared.b16 {%0,%1,%2,%3}, [%4];"
        : "=r"(r[0]), "=r"(r[1]), "=r"(r[2]), "=r"(r[3]) : "r"(addr));
}
__device__ __forceinline__ void ldsm4t(uint32_t r[4], uint32_t addr) {
    asm volatile("ldmatrix.sync.aligned.m8n8.x4.trans.shared.b16 {%0,%1,%2,%3}, [%4];"
        : "=r"(r[0]), "=r"(r[1]), "=r"(r[2]), "=r"(r[3]) : "r"(addr));
}
// not volatile: lets ptxas schedule HMMA around FMA/MUFU chains
__device__ __forceinline__ void mma_f16(float c[4], const uint32_t a[4],
                                        uint32_t b0, uint32_t b1) {
    asm("mma.sync.aligned.m16n8k16.row.col.f32.f16.f16.f32 "
        "{%0,%1,%2,%3}, {%4,%5,%6,%7}, {%8,%9}, {%0,%1,%2,%3};"
        : "+f"(c[0]), "+f"(c[1]), "+f"(c[2]), "+f"(c[3])
        : "r"(a[0]), "r"(a[1]), "r"(a[2]), "r"(a[3]), "r"(b0), "r"(b1));
}
__device__ __forceinline__ uint32_t packh(float lo, float hi) {
    uint32_t r;
    asm("cvt.rn.f16x2.f32 %0, %1, %2;" : "=r"(r) : "f"(hi), "f"(lo));
    return r;
}

// ================= pre-pass: K,V fp32 -> fp16 =================
__global__ __launch_bounds__(256)
void prep_kernel(const float* __restrict__ Kg, const float* __restrict__ Vg)
{
    const int i = blockIdx.x * 256 + threadIdx.x;      // per float4
    const int t = blockIdx.y;                          // 0=K 1=V
    const float4* src = (t == 0) ? (const float4*)Kg : (const float4*)Vg;
    uint2* hi = (t == 0) ? (uint2*)gKhi : (uint2*)gVhi;

    float4 v = src[i];
    uint2 h;
    h.x = packh(v.x, v.y);
    h.y = packh(v.z, v.w);
    hi[i] = h;
}

// ================= main attention kernel =================
__global__ __launch_bounds__(NTHR, 3)
void fattn_mma_kernel(float* __restrict__ Og, const float* __restrict__ Qg)
{
    extern __shared__ __align__(1024) uint8_t smem[];
    const uint32_t sb = smem_u32(smem);

    const int tid  = threadIdx.x;
    const int w    = tid >> 5;           // 0..3
    const int lane = tid & 31;
    const int lr   = lane & 15;
    const int lc   = (lane >> 4) << 3;
    const int quad = lane & 3;

    const int qt = (gridDim.x - 1) - blockIdx.x;   // heavy tiles first
    const int bh = blockIdx.y;
    const size_t rowbase = (size_t)bh * SEQ;       // 128B-row index base

    const int n_kv = qt + 1;                       // kv tiles 0..qt (BM == BN)

    // hoisted swizzled address components:
    // swz(row*128 + col) == row*128 + (col ^ ((lr&7)<<4))  for col in [0,128)
    const uint32_t xorp = (uint32_t)((lr & 7) << 4);
    uint32_t rowoff[4], coloff[4];
    #pragma unroll
    for (int g = 0; g < 4; g++) {
        rowoff[g] = (uint32_t)((g * 16 + lr) * 128);
        coloff[g] = ((uint32_t)(g * 32 + lc * 2)) ^ xorp;
    }

    // tile issuer: one 16KB stage (KHI|VHI); 8 cp.async per thread
    auto issue_tile = [&](int kt, uint32_t stg) {
        const size_t tb = (rowbase + (size_t)kt * BN) * 128;
        const uint8_t* kh = gKhi + tb;
        const uint8_t* vh = gVhi + tb;
        #pragma unroll
        for (int j = 0; j < 4; j++) {
            uint32_t idx = (uint32_t)(tid + j * NTHR);
            uint32_t off = idx << 4;                 // 0..8176
            uint32_t so  = sb + stg + swz(off);
            cpa16(so + P_KHI, kh + off);
            cpa16(so + P_VHI, vh + off);
        }
        CP_COMMIT();
    };

    issue_tile(0, 0);                   // tile 0 -> stage 0

    // ---- Q: load fp32, scale, fp16 pack, stage in stage-3 region (8KB) ----
    // Stage 3 is first overwritten by issue(tile 3) at iter 0, which happens
    // after BAR(0) — all warps have extracted their Q fragments by then.
    {
        const float* Qb = Qg + (rowbase + (size_t)qt * BM) * DH;
        #pragma unroll
        for (int it = 0; it < 8; it++) {
            int i  = tid + it * NTHR;   // 0..1023 float4
            int r  = i >> 4;
            int c4 = (i & 15) << 2;
            float4 v = *(const float4*)(Qb + r * DH + c4);
            uint2 h;
            h.x = packh(v.x * QSCALE, v.y * QSCALE);
            h.y = packh(v.z * QSCALE, v.w * QSCALE);
            *(uint2*)(smem + 3 * STAGE + swz((uint32_t)(r * 128 + c4 * 2))) = h;
        }
    }
    __syncthreads();

    uint32_t qh[4][4];
    #pragma unroll
    for (int ks = 0; ks < 4; ks++)
        ldsm4(qh[ks], sb + 3 * STAGE + rowoff[w] + coloff[ks]);

    // pre-issue tiles 1,2 into stages 1,2
    if (qt >= 1) issue_tile(1, STAGE);
    if (qt >= 2) issue_tile(2, 2 * STAGE);

    float o[8][4];
    #pragma unroll
    for (int n = 0; n < 8; n++)
        #pragma unroll
        for (int j = 0; j < 4; j++) o[n][j] = 0.f;
    float ol[4] = {0.f, 0.f, 0.f, 0.f};  // ones-column accum: row sums of P
    float m0 = -1e30f, m1 = -1e30f;

    const int qg0 = qt * BM + w * 16 + (lane >> 2);

    for (int kt = 0; kt < n_kv; kt++) {
        // exact tail-aware wait: pending-newer = min(qt-kt, 2)
        if (kt + 2 <= qt)      { CP_WAIT(2); }
        else if (kt + 1 <= qt) { CP_WAIT(1); }
        else                   { CP_WAIT(0); }
        __syncthreads();                 // single barrier: publish + WAR guard
        if (kt + 3 <= qt) issue_tile(kt + 3, (uint32_t)((kt + 3) & 3) * STAGE);

        const uint32_t stg = sb + (uint32_t)(kt & 3) * STAGE;

        // ---- S = Q.Khi  (single-pass fp16) ----
        float s[8][4];
        #pragma unroll
        for (int n = 0; n < 8; n++)
            #pragma unroll
            for (int j = 0; j < 4; j++) s[n][j] = 0.f;

        #pragma unroll
        for (int ks = 0; ks < 4; ks++) {
            #pragma unroll
            for (int kg = 0; kg < 4; kg++) {
                uint32_t bhf[4];
                ldsm4(bhf, stg + P_KHI + rowoff[kg] + coloff[ks]);
                mma_f16(s[2*kg],   qh[ks], bhf[0], bhf[2]);
                mma_f16(s[2*kg+1], qh[ks], bhf[1], bhf[3]);
            }
        }

        // ---- causal mask (diagonal tile only) ----
        if (kt == qt) {
            #pragma unroll
            for (int n = 0; n < 8; n++) {
                int kb = kt * BN + n * 8 + quad * 2;
                if (kb     > qg0)     s[n][0] = -30000.f;
                if (kb + 1 > qg0)     s[n][1] = -30000.f;
                if (kb     > qg0 + 8) s[n][2] = -30000.f;
                if (kb + 1 > qg0 + 8) s[n][3] = -30000.f;
            }
        }

        // ---- online softmax (log2 domain), l folded into PV via ones column ----
        float mx0 = s[0][0], mx1 = s[0][2];
        #pragma unroll
        for (int n = 0; n < 8; n++) {
            mx0 = fmaxf(mx0, fmaxf(s[n][0], s[n][1]));
            mx1 = fmaxf(mx1, fmaxf(s[n][2], s[n][3]));
        }
        mx0 = fmaxf(mx0, __shfl_xor_sync(0xffffffffu, mx0, 1));
        mx0 = fmaxf(mx0, __shfl_xor_sync(0xffffffffu, mx0, 2));
        mx1 = fmaxf(mx1, __shfl_xor_sync(0xffffffffu, mx1, 1));
        mx1 = fmaxf(mx1, __shfl_xor_sync(0xffffffffu, mx1, 2));

        if (__any_sync(0xffffffffu, (mx0 > m0) || (mx1 > m1))) {
            float mn0 = fmaxf(m0, mx0), mn1 = fmaxf(m1, mx1);
            float a0 = ex2(m0 - mn0), a1 = ex2(m1 - mn1);
            m0 = mn0; m1 = mn1;
            #pragma unroll
            for (int n = 0; n < 8; n++) {
                o[n][0] *= a0; o[n][1] *= a0;
                o[n][2] *= a1; o[n][3] *= a1;
            }
            ol[0] *= a0; ol[1] *= a0;
            ol[2] *= a1; ol[3] *= a1;
        }

        // ---- P = exp2(s - m) computed directly in fp16x2 A-fragments ----
        uint32_t pa[4][4];
        #pragma unroll
        for (int j = 0; j < 4; j++) {
            pa[j][0] = ex2h2(packh(s[2*j][0]   - m0, s[2*j][1]   - m0));
            pa[j][1] = ex2h2(packh(s[2*j][2]   - m1, s[2*j][3]   - m1));
            pa[j][2] = ex2h2(packh(s[2*j+1][0] - m0, s[2*j+1][1] - m0));
            pa[j][3] = ex2h2(packh(s[2*j+1][2] - m1, s[2*j+1][3] - m1));
        }

        // ---- ol += P.1 first (no ldsm dependency -> tensor starts at once),
        //      then O += P.Vhi ----
        #pragma unroll
        for (int ks = 0; ks < 4; ks++) {
            mma_f16(ol, pa[ks], ONESH2, ONESH2);
            #pragma unroll
            for (int dg = 0; dg < 4; dg++) {
                uint32_t vhf[4];
                ldsm4t(vhf, stg + P_VHI + rowoff[ks] + coloff[dg]);
                mma_f16(o[2*dg],   pa[ks], vhf[0], vhf[1]);
                mma_f16(o[2*dg+1], pa[ks], vhf[2], vhf[3]);
            }
        }
    }

    // ---- epilogue: normalize by ones-column sums ----
    float inv0 = 1.0f / ol[0], inv1 = 1.0f / ol[2];
    float* Orow0 = Og + (rowbase + qg0) * DH;
    float* Orow1 = Orow0 + 8 * DH;
    #pragma unroll
    for (int n = 0; n < 8; n++) {
        int d = n * 8 + quad * 2;
        *(float2*)(Orow0 + d) = make_float2(o[n][0] * inv0, o[n][1] * inv0);
        *(float2*)(Orow1 + d) = make_float2(o[n][2] * inv1, o[n][3] * inv1);
    }
}

extern "C" void kernel_launch(void* const* d_in, const int* in_sizes, int n_in,
                              void* d_out, int out_size)
{
    const float* Q = (const float*)d_in[0];
    const float* K = (const float*)d_in[1];
    const float* V = (const float*)d_in[2];
    float* O = (float*)d_out;

    dim3 pgrid(NELEM / 4 / 256, 2);     // (4096, 2): K and V
    prep_kernel<<<pgrid, 256>>>(K, V);

    cudaFuncSetAttribute(fattn_mma_kernel,
                         cudaFuncAttributeMaxDynamicSharedMemorySize, SMEM_BYTES);
    dim3 grid(SEQ / BM, BHN);           // (32, 32)
    fattn_mma_kernel<<<grid, NTHR, SMEM_BYTES>>>(O, Q);
}